// round 5
// baseline (speedup 1.0000x reference)
#include <cuda_runtime.h>
#include <cuda_bf16.h>
#include <math.h>
#include <stdint.h>

// Problem constants
constexpr int Bb  = 8;
constexpr int Tt  = 256;
constexpr int Ee  = 768;
constexpr int Nn  = 1024;
constexpr int Vv  = 32000;
constexpr int BT  = Bb * Tt;   // 2048

// ---------------- device scratch (no allocations allowed) ----------------
__device__ float g_X [BT * Nn];
__device__ float g_S [2][Bb * Nn];
__device__ float g_H [BT * Nn];
__device__ float g_Hn[BT * Nn];
__device__ float g_P [BT * Ee];
__device__ __nv_bfloat16 g_Ahi[BT * Ee];
__device__ __nv_bfloat16 g_Alo[BT * Ee];
__device__ __nv_bfloat16 g_Bhi[(size_t)Vv * Ee];  // w_head transposed [V][E]
__device__ __nv_bfloat16 g_Blo[(size_t)Vv * Ee];
__device__ int g_flags[128 * 8];   // one flag per CTA, 32B apart

__global__ void init_flags_kernel() {
    g_flags[threadIdx.x * 8] = 0;
}

// ---------------- release/acquire helpers ----------------
__device__ __forceinline__ int ld_acq(const int* p) {
    int v;
    asm volatile("ld.acquire.gpu.global.b32 %0, [%1];" : "=r"(v) : "l"(p) : "memory");
    return v;
}
__device__ __forceinline__ void st_rel(int* p, int v) {
    asm volatile("st.release.gpu.global.b32 [%0], %1;" :: "l"(p), "r"(v) : "memory");
}

// ---------------- persistent recurrent kernel (flag-synced) ----------------
constexpr int RNCTA = 128;
constexpr int RTPB  = 128;

__global__ void __launch_bounds__(RTPB, 1) recurrent_kernel(
    const float* __restrict__ w_bb, const float* __restrict__ b_bb)
{
    __shared__ float sV[Bb * Nn];
    __shared__ float sRed[4][16][33];

    const int tid   = threadIdx.x;
    const int lane  = tid & 31;
    const int warp  = tid >> 5;
    const int jbase = blockIdx.x * 8;
    const int j0    = jbase + warp * 2;

    float wreg[8][4][2];
#pragma unroll
    for (int i = 0; i < 8; i++) {
#pragma unroll
        for (int d = 0; d < 4; d++) {
            int k = 4 * lane + 128 * i + d;
            wreg[i][d][0] = w_bb[k * Nn + j0];
            wreg[i][d][1] = w_bb[k * Nn + j0 + 1];
        }
    }
    const float bias0 = b_bb[j0];
    const float bias1 = b_bb[j0 + 1];

    // phase 1: zero our slice of buf0
    if (tid < 64) {
        int b = tid >> 3, c = tid & 7;
        g_S[0][b * Nn + jbase + c] = 0.f;
    }
    __syncthreads();
    if (tid == 0) st_rel(&g_flags[blockIdx.x * 8], 1);

    const int* myflag = &g_flags[tid * 8];   // thread i watches CTA i (RTPB==RNCTA)

    int cur = 0;
#pragma unroll 1
    for (int p = 0; p < Tt * 4; p++) {
        // wait: all CTAs completed phase p+1 (i.e. substep p-1 / init)
        while (ld_acq(myflag) < p + 1) { }
        __syncthreads();

        const int t = p >> 2, step = p & 3;
        const float4* src = (const float4*)&g_S[cur][0];
        if (step == 0) {
            const float4* xs = (const float4*)g_X;
            for (int r = tid; r < (Bb * Nn) / 4; r += RTPB) {
                float4 a = __ldcg(src + r);
                int b  = r >> 8;
                int k4 = r & 255;
                float4 x = xs[(b * Tt + t) * (Nn / 4) + k4];
                a.x += x.x; a.y += x.y; a.z += x.z; a.w += x.w;
                ((float4*)sV)[r] = a;
            }
        } else {
            for (int r = tid; r < (Bb * Nn) / 4; r += RTPB) {
                ((float4*)sV)[r] = __ldcg(src + r);
            }
        }
        __syncthreads();

        float acc[16];
#pragma unroll
        for (int o = 0; o < 16; o++) acc[o] = 0.f;
#pragma unroll
        for (int i = 0; i < 8; i++) {
#pragma unroll
            for (int b = 0; b < Bb; b++) {
                float4 v = *(const float4*)&sV[b * Nn + 4 * lane + 128 * i];
                acc[b*2+0] = fmaf(v.x, wreg[i][0][0], acc[b*2+0]);
                acc[b*2+0] = fmaf(v.y, wreg[i][1][0], acc[b*2+0]);
                acc[b*2+0] = fmaf(v.z, wreg[i][2][0], acc[b*2+0]);
                acc[b*2+0] = fmaf(v.w, wreg[i][3][0], acc[b*2+0]);
                acc[b*2+1] = fmaf(v.x, wreg[i][0][1], acc[b*2+1]);
                acc[b*2+1] = fmaf(v.y, wreg[i][1][1], acc[b*2+1]);
                acc[b*2+1] = fmaf(v.z, wreg[i][2][1], acc[b*2+1]);
                acc[b*2+1] = fmaf(v.w, wreg[i][3][1], acc[b*2+1]);
            }
        }

#pragma unroll
        for (int o = 0; o < 16; o++) sRed[warp][o][lane] = acc[o];
        __syncwarp();

        const int nxt = cur ^ 1;
        if (lane < 16) {
            float s = 0.f;
#pragma unroll
            for (int l = 0; l < 32; l++) s += sRed[warp][lane][l];
            int b = lane >> 1, j = lane & 1;
            s += (j ? bias1 : bias0);
            float sn = tanhf(s);
            g_S[nxt][b * Nn + j0 + j] = sn;
            if (step == 3) g_H[(b * Tt + t) * Nn + j0 + j] = sn;
        }
        cur ^= 1;
        __syncthreads();
        if (tid == 0) st_rel(&g_flags[blockIdx.x * 8], p + 2);
    }
}

// ---------------- layernorm ----------------
__global__ void __launch_bounds__(256) ln_kernel(
    const float* __restrict__ in, float* __restrict__ outp,
    const float* __restrict__ gamma, const float* __restrict__ beta)
{
    const int row = blockIdx.x;
    const int tid = threadIdx.x;
    float4 v = ((const float4*)(in + row * Nn))[tid];
    float s = v.x + v.y + v.z + v.w;
    float q = v.x*v.x + v.y*v.y + v.z*v.z + v.w*v.w;
#pragma unroll
    for (int off = 16; off; off >>= 1) {
        s += __shfl_xor_sync(0xffffffffu, s, off);
        q += __shfl_xor_sync(0xffffffffu, q, off);
    }
    __shared__ float rs[8], rq[8];
    int lane = tid & 31, w = tid >> 5;
    if (lane == 0) { rs[w] = s; rq[w] = q; }
    __syncthreads();
    float ts = 0.f, tq = 0.f;
#pragma unroll
    for (int i = 0; i < 8; i++) { ts += rs[i]; tq += rq[i]; }
    float m   = ts * (1.f / Nn);
    float var = tq * (1.f / Nn) - m * m;
    float r   = rsqrtf(var + 1e-5f);
    float4 g  = ((const float4*)gamma)[tid];
    float4 be = ((const float4*)beta)[tid];
    float4 o;
    o.x = (v.x - m) * r * g.x + be.x;
    o.y = (v.y - m) * r * g.y + be.y;
    o.z = (v.z - m) * r * g.z + be.z;
    o.w = (v.w - m) * r * g.w + be.w;
    ((float4*)(outp + row * Nn))[tid] = o;
}

// ---------------- tiled fp32 GEMM (phases A and C) ----------------
template <bool GATHER, bool BIAS>
__global__ void __launch_bounds__(256) sgemm128(
    int M, int N, int K,
    const float* __restrict__ A, const float* __restrict__ Bm, float* __restrict__ C,
    const int* __restrict__ ids, const float* __restrict__ bias)
{
    constexpr int BM = 128, BN = 128, BK = 8;
    __shared__ float As[BK][BM];
    __shared__ float Bs[BK][BN];

    const int tid = threadIdx.x;
    const int bm  = blockIdx.y * BM;
    const int bn  = blockIdx.x * BN;

    const int innerRowA = tid >> 1;
    const int innerColA = (tid & 1) * 4;
    const int innerRowB = tid >> 5;
    const int innerColB = (tid & 31) * 4;

    const int tr = tid >> 4;
    const int tc = tid & 15;

    const int arow = bm + innerRowA;
    const int arowBase = (GATHER ? ids[arow] : arow) * K;

    float acc[8][8];
#pragma unroll
    for (int i = 0; i < 8; i++)
#pragma unroll
        for (int j = 0; j < 8; j++) acc[i][j] = 0.f;

    for (int kb = 0; kb < K; kb += BK) {
        float4 a = *(const float4*)(A + arowBase + kb + innerColA);
        float4 b = *(const float4*)(Bm + (kb + innerRowB) * N + bn + innerColB);
        As[innerColA + 0][innerRowA] = a.x;
        As[innerColA + 1][innerRowA] = a.y;
        As[innerColA + 2][innerRowA] = a.z;
        As[innerColA + 3][innerRowA] = a.w;
        *(float4*)&Bs[innerRowB][innerColB] = b;
        __syncthreads();

#pragma unroll
        for (int k = 0; k < BK; k++) {
            float rm[8], rn[8];
#pragma unroll
            for (int i = 0; i < 8; i++) rm[i] = As[k][tr * 8 + i];
#pragma unroll
            for (int j = 0; j < 8; j++) rn[j] = Bs[k][tc * 8 + j];
#pragma unroll
            for (int i = 0; i < 8; i++)
#pragma unroll
                for (int j = 0; j < 8; j++)
                    acc[i][j] = fmaf(rm[i], rn[j], acc[i][j]);
        }
        __syncthreads();
    }

#pragma unroll
    for (int i = 0; i < 8; i++) {
        int crow = (bm + tr * 8 + i) * N + bn + tc * 8;
#pragma unroll
        for (int j4 = 0; j4 < 2; j4++) {
            float4 v;
            v.x = acc[i][j4*4+0]; v.y = acc[i][j4*4+1];
            v.z = acc[i][j4*4+2]; v.w = acc[i][j4*4+3];
            if (BIAS) {
                float4 bb = *(const float4*)(bias + bn + tc * 8 + j4 * 4);
                v.x += bb.x; v.y += bb.y; v.z += bb.z; v.w += bb.w;
            }
            *(float4*)(C + crow + j4 * 4) = v;
        }
    }
}

// ---------------- fp32 -> split-bf16 conversions ----------------
__global__ void __launch_bounds__(256) convert_split_kernel(
    const float* __restrict__ src, __nv_bfloat16* __restrict__ hi,
    __nv_bfloat16* __restrict__ lo, int n)
{
    int i = blockIdx.x * blockDim.x + threadIdx.x;
    if (i < n) {
        float x = src[i];
        __nv_bfloat16 h = __float2bfloat16_rn(x);
        hi[i] = h;
        lo[i] = __float2bfloat16_rn(x - __bfloat162float(h));
    }
}

// transpose w_head [E=768, V=32000] -> [V, E] with hi/lo split
__global__ void __launch_bounds__(256) transpose_split_kernel(
    const float* __restrict__ src, __nv_bfloat16* __restrict__ hi,
    __nv_bfloat16* __restrict__ lo)
{
    __shared__ float tile[32][33];
    const int n0 = blockIdx.x * 32;
    const int k0 = blockIdx.y * 32;
    const int tx = threadIdx.x;
    const int ty = threadIdx.y;
#pragma unroll
    for (int j = 0; j < 32; j += 8)
        tile[ty + j][tx] = src[(size_t)(k0 + ty + j) * Vv + n0 + tx];
    __syncthreads();
#pragma unroll
    for (int j = 0; j < 32; j += 8) {
        float x = tile[tx][ty + j];
        __nv_bfloat16 h = __float2bfloat16_rn(x);
        size_t o = (size_t)(n0 + ty + j) * Ee + k0 + tx;
        hi[o] = h;
        lo[o] = __float2bfloat16_rn(x - __bfloat162float(h));
    }
}

// ---------------- HMMA head GEMM (cp.async double-buffered) ----------------
constexpr int HSTR   = 40;                  // smem row stride in bf16
constexpr int HTILE  = 128 * HSTR * 2;      // 10240 B per operand tile
constexpr int HSTAGE = HTILE * 4;           // 40960 B per stage
constexpr int HG_SMEM = HSTAGE * 2;         // 81920 B

__device__ __forceinline__ uint32_t smem_u32(const void* p) {
    uint32_t a;
    asm("{ .reg .u64 t; cvta.to.shared.u64 t, %1; cvt.u32.u64 %0, t; }" : "=r"(a) : "l"(p));
    return a;
}
__device__ __forceinline__ void cp16(uint32_t dst, const void* src) {
    asm volatile("cp.async.cg.shared.global [%0], [%1], 16;" :: "r"(dst), "l"(src));
}
__device__ __forceinline__ void cp_commit() {
    asm volatile("cp.async.commit_group;" ::: "memory");
}
template<int N>
__device__ __forceinline__ void cp_wait() {
    asm volatile("cp.async.wait_group %0;" :: "n"(N) : "memory");
}
__device__ __forceinline__ uint32_t lds32(const __nv_bfloat16* p) {
    return *(const uint32_t*)p;
}
__device__ __forceinline__ void mma16816(float* c, const uint32_t* a,
                                         uint32_t b0, uint32_t b1) {
    asm volatile(
        "mma.sync.aligned.m16n8k16.row.col.f32.bf16.bf16.f32 "
        "{%0,%1,%2,%3}, {%4,%5,%6,%7}, {%8,%9}, {%0,%1,%2,%3};"
        : "+f"(c[0]), "+f"(c[1]), "+f"(c[2]), "+f"(c[3])
        : "r"(a[0]), "r"(a[1]), "r"(a[2]), "r"(a[3]), "r"(b0), "r"(b1));
}

__global__ void __launch_bounds__(256, 2) head_mma_kernel(
    const __nv_bfloat16* __restrict__ Ahi, const __nv_bfloat16* __restrict__ Alo,
    const __nv_bfloat16* __restrict__ Bhi, const __nv_bfloat16* __restrict__ Blo,
    float* __restrict__ out)
{
    extern __shared__ char hsm[];
    const uint32_t sbase = smem_u32(hsm);

    const int tid  = threadIdx.x;
    const int warp = tid >> 5;
    const int lane = tid & 31;
    const int m0 = blockIdx.y * 128;
    const int n0 = blockIdx.x * 128;
    const int wm = (warp >> 1) * 32;
    const int wn = (warp & 1) * 64;
    const int g  = lane >> 2;
    const int t  = lane & 3;

    // loader mapping: each thread owns one (row, 16-col half)
    const int lr = tid >> 1;
    const int lc = (tid & 1) * 16;
    const uint32_t soff = (uint32_t)(lr * HSTR + lc) * 2;
    const __nv_bfloat16* gsrc[4];
    gsrc[0] = Ahi + (size_t)(m0 + lr) * Ee + lc;
    gsrc[1] = Alo + (size_t)(m0 + lr) * Ee + lc;
    gsrc[2] = Bhi + (size_t)(n0 + lr) * Ee + lc;
    gsrc[3] = Blo + (size_t)(n0 + lr) * Ee + lc;

    float c[2][8][4];
#pragma unroll
    for (int i = 0; i < 2; i++)
#pragma unroll
        for (int j = 0; j < 8; j++)
#pragma unroll
            for (int q = 0; q < 4; q++) c[i][j][q] = 0.f;

    // prologue: stage 0
    {
#pragma unroll
        for (int a = 0; a < 4; a++) {
            uint32_t d = sbase + a * HTILE + soff;
            cp16(d, gsrc[a]);
            cp16(d + 16, gsrc[a] + 8);
        }
        cp_commit();
    }

#pragma unroll 1
    for (int it = 0; it < 24; it++) {
        if (it + 1 < 24) {
            const int st = (it + 1) & 1;
            const int kb = (it + 1) * 32;
#pragma unroll
            for (int a = 0; a < 4; a++) {
                uint32_t d = sbase + st * HSTAGE + a * HTILE + soff;
                cp16(d, gsrc[a] + kb);
                cp16(d + 16, gsrc[a] + kb + 8);
            }
            cp_commit();
            cp_wait<1>();
        } else {
            cp_wait<0>();
        }
        __syncthreads();

        const char* stg = hsm + (it & 1) * HSTAGE;
        const __nv_bfloat16* sAh = (const __nv_bfloat16*)(stg);
        const __nv_bfloat16* sAl = (const __nv_bfloat16*)(stg + HTILE);
        const __nv_bfloat16* sBh = (const __nv_bfloat16*)(stg + 2 * HTILE);
        const __nv_bfloat16* sBl = (const __nv_bfloat16*)(stg + 3 * HTILE);

#pragma unroll
        for (int kk = 0; kk < 32; kk += 16) {
            uint32_t ah[2][4], al[2][4];
#pragma unroll
            for (int i = 0; i < 2; i++) {
                int r0 = (wm + 16 * i + g) * HSTR + kk + 2 * t;
                int r1 = (wm + 16 * i + g + 8) * HSTR + kk + 2 * t;
                ah[i][0] = lds32(&sAh[r0]);
                ah[i][1] = lds32(&sAh[r1]);
                ah[i][2] = lds32(&sAh[r0 + 8]);
                ah[i][3] = lds32(&sAh[r1 + 8]);
                al[i][0] = lds32(&sAl[r0]);
                al[i][1] = lds32(&sAl[r1]);
                al[i][2] = lds32(&sAl[r0 + 8]);
                al[i][3] = lds32(&sAl[r1 + 8]);
            }
#pragma unroll
            for (int j = 0; j < 8; j++) {
                int nb = (wn + 8 * j + g) * HSTR + kk + 2 * t;
                uint32_t bh0 = lds32(&sBh[nb]);
                uint32_t bh1 = lds32(&sBh[nb + 8]);
                uint32_t bl0 = lds32(&sBl[nb]);
                uint32_t bl1 = lds32(&sBl[nb + 8]);
#pragma unroll
                for (int i = 0; i < 2; i++) {
                    mma16816(c[i][j], ah[i], bh0, bh1);
                    mma16816(c[i][j], ah[i], bl0, bl1);
                    mma16816(c[i][j], al[i], bh0, bh1);
                }
            }
        }
        __syncthreads();
    }

    // epilogue: direct float2 stores
#pragma unroll
    for (int i = 0; i < 2; i++) {
#pragma unroll
        for (int j = 0; j < 8; j++) {
            int row = m0 + wm + 16 * i + g;
            int col = n0 + wn + 8 * j + 2 * t;
            float2 v0 = make_float2(c[i][j][0], c[i][j][1]);
            float2 v1 = make_float2(c[i][j][2], c[i][j][3]);
            *(float2*)(out + (size_t)row * Vv + col)       = v0;
            *(float2*)(out + (size_t)(row + 8) * Vv + col) = v1;
        }
    }
}

// ---------------- launch ----------------
extern "C" void kernel_launch(void* const* d_in, const int* in_sizes, int n_in,
                              void* d_out, int out_size)
{
    const int*   ids    = (const int*)  d_in[0];
    const float* emb    = (const float*)d_in[1];
    const float* w_in   = (const float*)d_in[2];
    const float* b_in   = (const float*)d_in[3];
    const float* w_bb   = (const float*)d_in[4];
    const float* b_bb   = (const float*)d_in[5];
    const float* gamma  = (const float*)d_in[6];
    const float* beta   = (const float*)d_in[7];
    const float* w_out  = (const float*)d_in[8];
    const float* w_head = (const float*)d_in[9];
    float* out = (float*)d_out;

    float *pX = nullptr, *pH = nullptr, *pHn = nullptr, *pP = nullptr;
    __nv_bfloat16 *pAhi = nullptr, *pAlo = nullptr, *pBhi = nullptr, *pBlo = nullptr;
    cudaGetSymbolAddress((void**)&pX,   g_X);
    cudaGetSymbolAddress((void**)&pH,   g_H);
    cudaGetSymbolAddress((void**)&pHn,  g_Hn);
    cudaGetSymbolAddress((void**)&pP,   g_P);
    cudaGetSymbolAddress((void**)&pAhi, g_Ahi);
    cudaGetSymbolAddress((void**)&pAlo, g_Alo);
    cudaGetSymbolAddress((void**)&pBhi, g_Bhi);
    cudaGetSymbolAddress((void**)&pBlo, g_Blo);

    cudaFuncSetAttribute(head_mma_kernel,
                         cudaFuncAttributeMaxDynamicSharedMemorySize, HG_SMEM);

    // 0. reset sync flags (device globals persist across graph replays)
    init_flags_kernel<<<1, 128>>>();

    // 0b. transpose + split w_head
    {
        dim3 g(Vv / 32, Ee / 32), b(32, 8);
        transpose_split_kernel<<<g, b>>>(w_head, pBhi, pBlo);
    }

    // 1. X = emb[ids] @ w_in + b_in
    {
        dim3 g(Nn / 128, BT / 128);
        sgemm128<true, true><<<g, 256>>>(BT, Nn, Ee, emb, w_in, pX, ids, b_in);
    }

    // 2. recurrent scan (flag-synced persistent kernel)
    recurrent_kernel<<<RNCTA, RTPB>>>(w_bb, b_bb);

    // 3. layernorm
    ln_kernel<<<BT, 256>>>(pH, pHn, gamma, beta);

    // 4. P = Hn @ w_out
    {
        dim3 g(Ee / 128, BT / 128);
        sgemm128<false, false><<<g, 256>>>(BT, Ee, Nn, pHn, w_out, pP, nullptr, nullptr);
    }

    // 5. split P into bf16 hi/lo
    convert_split_kernel<<<(BT * Ee + 255) / 256, 256>>>(pP, pAhi, pAlo, BT * Ee);

    // 6. logits = P @ w_head via pipelined HMMA split-bf16
    {
        dim3 g(Vv / 128, BT / 128);
        head_mma_kernel<<<g, 256, HG_SMEM>>>(pAhi, pAlo, pBhi, pBlo, out);
    }
}

// round 6
// speedup vs baseline: 1.0430x; 1.0430x over previous
#include <cuda_runtime.h>
#include <cuda_bf16.h>
#include <math.h>
#include <stdint.h>

// Problem constants
constexpr int Bb  = 8;
constexpr int Tt  = 256;
constexpr int Ee  = 768;
constexpr int Nn  = 1024;
constexpr int Vv  = 32000;
constexpr int BT  = Bb * Tt;   // 2048

// ---------------- device scratch (no allocations allowed) ----------------
__device__ float g_X [BT * Nn];
__device__ float g_S [2][Bb * Nn];
__device__ float g_H [BT * Nn];
__device__ float g_Hn[BT * Nn];
__device__ float g_P [BT * Ee];
__device__ __nv_bfloat16 g_Ahi[BT * Ee];
__device__ __nv_bfloat16 g_Alo[BT * Ee];
__device__ __nv_bfloat16 g_Bhi[(size_t)Vv * Ee];  // w_head transposed [V][E]
__device__ __nv_bfloat16 g_Blo[(size_t)Vv * Ee];
__device__ unsigned g_cnt1[8 * 64];   // 8 group counters, 256B apart
__device__ unsigned g_cnt2;
__device__ volatile unsigned g_gen;

__global__ void init_barrier_kernel() {
    if (threadIdx.x < 8) g_cnt1[threadIdx.x * 64] = 0u;
    if (threadIdx.x == 0) { g_cnt2 = 0u; g_gen = 0u; }
}

// ---------------- persistent recurrent kernel ----------------
constexpr int RNCTA = 128;
constexpr int RTPB  = 128;

// Two-level tree barrier: 8 groups of 16 CTAs -> 1 level-2 counter -> g_gen.
__device__ __forceinline__ void gridbar(int grp) {
    __syncthreads();
    if (threadIdx.x == 0) {
        unsigned my = g_gen;
        __threadfence();
        if (atomicAdd(&g_cnt1[grp * 64], 1u) == 15u) {
            g_cnt1[grp * 64] = 0u;
            if (atomicAdd(&g_cnt2, 1u) == 7u) {
                g_cnt2 = 0u;
                __threadfence();
                g_gen = my + 1u;
            }
        }
        while (g_gen == my) { }
    }
    __syncthreads();
}

__global__ void __launch_bounds__(RTPB, 1) recurrent_kernel(
    const float* __restrict__ w_bb, const float* __restrict__ b_bb)
{
    __shared__ float sV[Bb * Nn];
    __shared__ float sRed[4][16][33];

    const int tid   = threadIdx.x;
    const int lane  = tid & 31;
    const int warp  = tid >> 5;
    const int jbase = blockIdx.x * 8;
    const int j0    = jbase + warp * 2;
    const int grp   = blockIdx.x >> 4;   // 8 groups of 16 CTAs

    float wreg[8][4][2];
#pragma unroll
    for (int i = 0; i < 8; i++) {
#pragma unroll
        for (int d = 0; d < 4; d++) {
            int k = 4 * lane + 128 * i + d;
            wreg[i][d][0] = w_bb[k * Nn + j0];
            wreg[i][d][1] = w_bb[k * Nn + j0 + 1];
        }
    }
    const float bias0 = b_bb[j0];
    const float bias1 = b_bb[j0 + 1];

    if (tid < 64) {
        int b = tid >> 3, c = tid & 7;
        g_S[0][b * Nn + jbase + c] = 0.f;
    }
    gridbar(grp);

    int cur = 0;
#pragma unroll 1
    for (int t = 0; t < Tt; t++) {
#pragma unroll 1
        for (int step = 0; step < 4; step++) {
            const float4* src = (const float4*)&g_S[cur][0];
            if (step == 0) {
                const float4* xs = (const float4*)g_X;
                for (int r = tid; r < (Bb * Nn) / 4; r += RTPB) {
                    float4 a = __ldcg(src + r);
                    int b  = r >> 8;
                    int k4 = r & 255;
                    float4 x = xs[(b * Tt + t) * (Nn / 4) + k4];
                    a.x += x.x; a.y += x.y; a.z += x.z; a.w += x.w;
                    ((float4*)sV)[r] = a;
                }
            } else {
                for (int r = tid; r < (Bb * Nn) / 4; r += RTPB) {
                    ((float4*)sV)[r] = __ldcg(src + r);
                }
            }
            __syncthreads();

            float acc[16];
#pragma unroll
            for (int o = 0; o < 16; o++) acc[o] = 0.f;
#pragma unroll
            for (int i = 0; i < 8; i++) {
#pragma unroll
                for (int b = 0; b < Bb; b++) {
                    float4 v = *(const float4*)&sV[b * Nn + 4 * lane + 128 * i];
                    acc[b*2+0] = fmaf(v.x, wreg[i][0][0], acc[b*2+0]);
                    acc[b*2+0] = fmaf(v.y, wreg[i][1][0], acc[b*2+0]);
                    acc[b*2+0] = fmaf(v.z, wreg[i][2][0], acc[b*2+0]);
                    acc[b*2+0] = fmaf(v.w, wreg[i][3][0], acc[b*2+0]);
                    acc[b*2+1] = fmaf(v.x, wreg[i][0][1], acc[b*2+1]);
                    acc[b*2+1] = fmaf(v.y, wreg[i][1][1], acc[b*2+1]);
                    acc[b*2+1] = fmaf(v.z, wreg[i][2][1], acc[b*2+1]);
                    acc[b*2+1] = fmaf(v.w, wreg[i][3][1], acc[b*2+1]);
                }
            }

#pragma unroll
            for (int o = 0; o < 16; o++) sRed[warp][o][lane] = acc[o];
            __syncwarp();

            int nxt = cur ^ 1;
            if (lane < 16) {
                float s = 0.f;
#pragma unroll
                for (int l = 0; l < 32; l++) s += sRed[warp][lane][l];
                int b = lane >> 1, j = lane & 1;
                s += (j ? bias1 : bias0);
                float sn = tanhf(s);
                g_S[nxt][b * Nn + j0 + j] = sn;
                if (step == 3) g_H[(b * Tt + t) * Nn + j0 + j] = sn;
            }
            cur ^= 1;
            gridbar(grp);
        }
    }
}

// ---------------- layernorm ----------------
__global__ void __launch_bounds__(256) ln_kernel(
    const float* __restrict__ in, float* __restrict__ outp,
    const float* __restrict__ gamma, const float* __restrict__ beta)
{
    const int row = blockIdx.x;
    const int tid = threadIdx.x;
    float4 v = ((const float4*)(in + row * Nn))[tid];
    float s = v.x + v.y + v.z + v.w;
    float q = v.x*v.x + v.y*v.y + v.z*v.z + v.w*v.w;
#pragma unroll
    for (int off = 16; off; off >>= 1) {
        s += __shfl_xor_sync(0xffffffffu, s, off);
        q += __shfl_xor_sync(0xffffffffu, q, off);
    }
    __shared__ float rs[8], rq[8];
    int lane = tid & 31, w = tid >> 5;
    if (lane == 0) { rs[w] = s; rq[w] = q; }
    __syncthreads();
    float ts = 0.f, tq = 0.f;
#pragma unroll
    for (int i = 0; i < 8; i++) { ts += rs[i]; tq += rq[i]; }
    float m   = ts * (1.f / Nn);
    float var = tq * (1.f / Nn) - m * m;
    float r   = rsqrtf(var + 1e-5f);
    float4 g  = ((const float4*)gamma)[tid];
    float4 be = ((const float4*)beta)[tid];
    float4 o;
    o.x = (v.x - m) * r * g.x + be.x;
    o.y = (v.y - m) * r * g.y + be.y;
    o.z = (v.z - m) * r * g.z + be.z;
    o.w = (v.w - m) * r * g.w + be.w;
    ((float4*)(outp + row * Nn))[tid] = o;
}

// ---------------- tiled fp32 GEMM (phases A and C) ----------------
template <bool GATHER, bool BIAS>
__global__ void __launch_bounds__(256) sgemm128(
    int M, int N, int K,
    const float* __restrict__ A, const float* __restrict__ Bm, float* __restrict__ C,
    const int* __restrict__ ids, const float* __restrict__ bias)
{
    constexpr int BM = 128, BN = 128, BK = 8;
    __shared__ float As[BK][BM];
    __shared__ float Bs[BK][BN];

    const int tid = threadIdx.x;
    const int bm  = blockIdx.y * BM;
    const int bn  = blockIdx.x * BN;

    const int innerRowA = tid >> 1;
    const int innerColA = (tid & 1) * 4;
    const int innerRowB = tid >> 5;
    const int innerColB = (tid & 31) * 4;

    const int tr = tid >> 4;
    const int tc = tid & 15;

    const int arow = bm + innerRowA;
    const int arowBase = (GATHER ? ids[arow] : arow) * K;

    float acc[8][8];
#pragma unroll
    for (int i = 0; i < 8; i++)
#pragma unroll
        for (int j = 0; j < 8; j++) acc[i][j] = 0.f;

    for (int kb = 0; kb < K; kb += BK) {
        float4 a = *(const float4*)(A + arowBase + kb + innerColA);
        float4 b = *(const float4*)(Bm + (kb + innerRowB) * N + bn + innerColB);
        As[innerColA + 0][innerRowA] = a.x;
        As[innerColA + 1][innerRowA] = a.y;
        As[innerColA + 2][innerRowA] = a.z;
        As[innerColA + 3][innerRowA] = a.w;
        *(float4*)&Bs[innerRowB][innerColB] = b;
        __syncthreads();

#pragma unroll
        for (int k = 0; k < BK; k++) {
            float rm[8], rn[8];
#pragma unroll
            for (int i = 0; i < 8; i++) rm[i] = As[k][tr * 8 + i];
#pragma unroll
            for (int j = 0; j < 8; j++) rn[j] = Bs[k][tc * 8 + j];
#pragma unroll
            for (int i = 0; i < 8; i++)
#pragma unroll
                for (int j = 0; j < 8; j++)
                    acc[i][j] = fmaf(rm[i], rn[j], acc[i][j]);
        }
        __syncthreads();
    }

#pragma unroll
    for (int i = 0; i < 8; i++) {
        int crow = (bm + tr * 8 + i) * N + bn + tc * 8;
#pragma unroll
        for (int j4 = 0; j4 < 2; j4++) {
            float4 v;
            v.x = acc[i][j4*4+0]; v.y = acc[i][j4*4+1];
            v.z = acc[i][j4*4+2]; v.w = acc[i][j4*4+3];
            if (BIAS) {
                float4 bb = *(const float4*)(bias + bn + tc * 8 + j4 * 4);
                v.x += bb.x; v.y += bb.y; v.z += bb.z; v.w += bb.w;
            }
            *(float4*)(C + crow + j4 * 4) = v;
        }
    }
}

// ---------------- fp32 -> split-bf16 conversions ----------------
__global__ void __launch_bounds__(256) convert_split_kernel(
    const float* __restrict__ src, __nv_bfloat16* __restrict__ hi,
    __nv_bfloat16* __restrict__ lo, int n)
{
    int i = blockIdx.x * blockDim.x + threadIdx.x;
    if (i < n) {
        float x = src[i];
        __nv_bfloat16 h = __float2bfloat16_rn(x);
        hi[i] = h;
        lo[i] = __float2bfloat16_rn(x - __bfloat162float(h));
    }
}

// transpose w_head [E=768, V=32000] -> [V, E] with hi/lo split
__global__ void __launch_bounds__(256) transpose_split_kernel(
    const float* __restrict__ src, __nv_bfloat16* __restrict__ hi,
    __nv_bfloat16* __restrict__ lo)
{
    __shared__ float tile[32][33];
    const int n0 = blockIdx.x * 32;
    const int k0 = blockIdx.y * 32;
    const int tx = threadIdx.x;
    const int ty = threadIdx.y;
#pragma unroll
    for (int j = 0; j < 32; j += 8)
        tile[ty + j][tx] = src[(size_t)(k0 + ty + j) * Vv + n0 + tx];
    __syncthreads();
#pragma unroll
    for (int j = 0; j < 32; j += 8) {
        float x = tile[tx][ty + j];
        __nv_bfloat16 h = __float2bfloat16_rn(x);
        size_t o = (size_t)(n0 + ty + j) * Ee + k0 + tx;
        hi[o] = h;
        lo[o] = __float2bfloat16_rn(x - __bfloat162float(h));
    }
}

// ---------------- HMMA head GEMM: out[2048,32000] = P @ w_head ----------------
constexpr int HSTR = 40;   // smem row stride in bf16 (conflict-free fragment loads)

__device__ __forceinline__ uint32_t lds32(const __nv_bfloat16* p) {
    return *(const uint32_t*)p;
}
__device__ __forceinline__ void mma16816(float* c, const uint32_t* a,
                                         uint32_t b0, uint32_t b1) {
    asm volatile(
        "mma.sync.aligned.m16n8k16.row.col.f32.bf16.bf16.f32 "
        "{%0,%1,%2,%3}, {%4,%5,%6,%7}, {%8,%9}, {%0,%1,%2,%3};"
        : "+f"(c[0]), "+f"(c[1]), "+f"(c[2]), "+f"(c[3])
        : "r"(a[0]), "r"(a[1]), "r"(a[2]), "r"(a[3]), "r"(b0), "r"(b1));
}

__global__ void __launch_bounds__(256) head_mma_kernel(
    const __nv_bfloat16* __restrict__ Ahi, const __nv_bfloat16* __restrict__ Alo,
    const __nv_bfloat16* __restrict__ Bhi, const __nv_bfloat16* __restrict__ Blo,
    float* __restrict__ out)
{
    __shared__ __nv_bfloat16 sAh[128 * HSTR];
    __shared__ __nv_bfloat16 sAl[128 * HSTR];
    __shared__ __nv_bfloat16 sBh[128 * HSTR];
    __shared__ __nv_bfloat16 sBl[128 * HSTR];

    const int tid  = threadIdx.x;
    const int warp = tid >> 5;
    const int lane = tid & 31;
    const int m0 = blockIdx.y * 128;
    const int n0 = blockIdx.x * 128;
    const int wm = (warp >> 1) * 32;
    const int wn = (warp & 1) * 64;
    const int g  = lane >> 2;
    const int t  = lane & 3;

    float c[2][8][4];
#pragma unroll
    for (int i = 0; i < 2; i++)
#pragma unroll
        for (int j = 0; j < 8; j++)
#pragma unroll
            for (int q = 0; q < 4; q++) c[i][j][q] = 0.f;

    const int lr = tid >> 1;
    const int lc = (tid & 1) * 16;
    const __nv_bfloat16* gAh = Ahi + (size_t)(m0 + lr) * Ee + lc;
    const __nv_bfloat16* gAl = Alo + (size_t)(m0 + lr) * Ee + lc;
    const __nv_bfloat16* gBh = Bhi + (size_t)(n0 + lr) * Ee + lc;
    const __nv_bfloat16* gBl = Blo + (size_t)(n0 + lr) * Ee + lc;
    __nv_bfloat16* stA_h = &sAh[lr * HSTR + lc];
    __nv_bfloat16* stA_l = &sAl[lr * HSTR + lc];
    __nv_bfloat16* stB_h = &sBh[lr * HSTR + lc];
    __nv_bfloat16* stB_l = &sBl[lr * HSTR + lc];

#pragma unroll 1
    for (int kb = 0; kb < Ee; kb += 32) {
        *(uint4*)(stA_h)     = *(const uint4*)(gAh + kb);
        *(uint4*)(stA_h + 8) = *(const uint4*)(gAh + kb + 8);
        *(uint4*)(stA_l)     = *(const uint4*)(gAl + kb);
        *(uint4*)(stA_l + 8) = *(const uint4*)(gAl + kb + 8);
        *(uint4*)(stB_h)     = *(const uint4*)(gBh + kb);
        *(uint4*)(stB_h + 8) = *(const uint4*)(gBh + kb + 8);
        *(uint4*)(stB_l)     = *(const uint4*)(gBl + kb);
        *(uint4*)(stB_l + 8) = *(const uint4*)(gBl + kb + 8);
        __syncthreads();

#pragma unroll
        for (int kk = 0; kk < 32; kk += 16) {
            uint32_t ah[2][4], al[2][4];
#pragma unroll
            for (int i = 0; i < 2; i++) {
                int r0 = (wm + 16 * i + g) * HSTR + kk + 2 * t;
                int r1 = (wm + 16 * i + g + 8) * HSTR + kk + 2 * t;
                ah[i][0] = lds32(&sAh[r0]);
                ah[i][1] = lds32(&sAh[r1]);
                ah[i][2] = lds32(&sAh[r0 + 8]);
                ah[i][3] = lds32(&sAh[r1 + 8]);
                al[i][0] = lds32(&sAl[r0]);
                al[i][1] = lds32(&sAl[r1]);
                al[i][2] = lds32(&sAl[r0 + 8]);
                al[i][3] = lds32(&sAl[r1 + 8]);
            }
#pragma unroll
            for (int j = 0; j < 8; j++) {
                int nb = (wn + 8 * j + g) * HSTR + kk + 2 * t;
                uint32_t bh0 = lds32(&sBh[nb]);
                uint32_t bh1 = lds32(&sBh[nb + 8]);
                uint32_t bl0 = lds32(&sBl[nb]);
                uint32_t bl1 = lds32(&sBl[nb + 8]);
#pragma unroll
                for (int i = 0; i < 2; i++) {
                    mma16816(c[i][j], ah[i], bh0, bh1);
                    mma16816(c[i][j], ah[i], bl0, bl1);
                    mma16816(c[i][j], al[i], bh0, bh1);
                }
            }
        }
        __syncthreads();
    }

#pragma unroll
    for (int i = 0; i < 2; i++) {
#pragma unroll
        for (int j = 0; j < 8; j++) {
            int row = m0 + wm + 16 * i + g;
            int col = n0 + wn + 8 * j + 2 * t;
            float2 v0 = make_float2(c[i][j][0], c[i][j][1]);
            float2 v1 = make_float2(c[i][j][2], c[i][j][3]);
            *(float2*)(out + (size_t)row * Vv + col)       = v0;
            *(float2*)(out + (size_t)(row + 8) * Vv + col) = v1;
        }
    }
}

// ---------------- launch ----------------
extern "C" void kernel_launch(void* const* d_in, const int* in_sizes, int n_in,
                              void* d_out, int out_size)
{
    const int*   ids    = (const int*)  d_in[0];
    const float* emb    = (const float*)d_in[1];
    const float* w_in   = (const float*)d_in[2];
    const float* b_in   = (const float*)d_in[3];
    const float* w_bb   = (const float*)d_in[4];
    const float* b_bb   = (const float*)d_in[5];
    const float* gamma  = (const float*)d_in[6];
    const float* beta   = (const float*)d_in[7];
    const float* w_out  = (const float*)d_in[8];
    const float* w_head = (const float*)d_in[9];
    float* out = (float*)d_out;

    float *pX = nullptr, *pH = nullptr, *pHn = nullptr, *pP = nullptr;
    __nv_bfloat16 *pAhi = nullptr, *pAlo = nullptr, *pBhi = nullptr, *pBlo = nullptr;
    cudaGetSymbolAddress((void**)&pX,   g_X);
    cudaGetSymbolAddress((void**)&pH,   g_H);
    cudaGetSymbolAddress((void**)&pHn,  g_Hn);
    cudaGetSymbolAddress((void**)&pP,   g_P);
    cudaGetSymbolAddress((void**)&pAhi, g_Ahi);
    cudaGetSymbolAddress((void**)&pAlo, g_Alo);
    cudaGetSymbolAddress((void**)&pBhi, g_Bhi);
    cudaGetSymbolAddress((void**)&pBlo, g_Blo);

    // 0. reset barrier state (device globals persist across graph replays)
    init_barrier_kernel<<<1, 32>>>();

    // 0b. transpose + split w_head
    {
        dim3 g(Vv / 32, Ee / 32), b(32, 8);
        transpose_split_kernel<<<g, b>>>(w_head, pBhi, pBlo);
    }

    // 1. X = emb[ids] @ w_in + b_in
    {
        dim3 g(Nn / 128, BT / 128);
        sgemm128<true, true><<<g, 256>>>(BT, Nn, Ee, emb, w_in, pX, ids, b_in);
    }

    // 2. recurrent scan (tree-barrier persistent kernel)
    recurrent_kernel<<<RNCTA, RTPB>>>(w_bb, b_bb);

    // 3. layernorm
    ln_kernel<<<BT, 256>>>(pH, pHn, gamma, beta);

    // 4. P = Hn @ w_out
    {
        dim3 g(Ee / 128, BT / 128);
        sgemm128<false, false><<<g, 256>>>(BT, Ee, Nn, pHn, w_out, pP, nullptr, nullptr);
    }

    // 5. split P into bf16 hi/lo
    convert_split_kernel<<<(BT * Ee + 255) / 256, 256>>>(pP, pAhi, pAlo, BT * Ee);

    // 6. logits = P @ w_head via HMMA split-bf16
    {
        dim3 g(Vv / 128, BT / 128);
        head_mma_kernel<<<g, 256>>>(pAhi, pAlo, pBhi, pBlo, out);
    }
}

// round 7
// speedup vs baseline: 1.2495x; 1.1979x over previous
#include <cuda_runtime.h>
#include <cuda_bf16.h>
#include <math.h>
#include <stdint.h>

// Problem constants
constexpr int Bb  = 8;
constexpr int Tt  = 256;
constexpr int Ee  = 768;
constexpr int Nn  = 1024;
constexpr int Vv  = 32000;
constexpr int BT  = Bb * Tt;   // 2048

// ---------------- device scratch (no allocations allowed) ----------------
__device__ float g_X [BT * Nn];
__device__ float g_S [2][Bb * Nn];
__device__ float g_H [BT * Nn];
__device__ float g_Hn[BT * Nn];
__device__ float g_P [BT * Ee];
__device__ __nv_bfloat16 g_Ahi[BT * Ee];
__device__ __nv_bfloat16 g_Alo[BT * Ee];
__device__ __nv_bfloat16 g_Bhi[(size_t)Vv * Ee];  // w_head transposed [V][E]
__device__ __nv_bfloat16 g_Blo[(size_t)Vv * Ee];
__device__ unsigned g_count;
__device__ volatile unsigned g_gen;

__global__ void init_barrier_kernel() {
    g_count = 0u;
    g_gen   = 0u;
}

// ---------------- cp.async helpers ----------------
__device__ __forceinline__ uint32_t smem_u32(const void* p) {
    uint32_t a;
    asm("{ .reg .u64 t; cvta.to.shared.u64 t, %1; cvt.u32.u64 %0, t; }" : "=r"(a) : "l"(p));
    return a;
}
__device__ __forceinline__ void cp16(uint32_t dst, const void* src) {
    asm volatile("cp.async.cg.shared.global [%0], [%1], 16;" :: "r"(dst), "l"(src));
}
__device__ __forceinline__ void cp_commit() {
    asm volatile("cp.async.commit_group;" ::: "memory");
}
template<int N>
__device__ __forceinline__ void cp_wait() {
    asm volatile("cp.async.wait_group %0;" :: "n"(N) : "memory");
}

// ---------------- persistent recurrent kernel ----------------
constexpr int RNCTA = 128;
constexpr int RTPB  = 128;

// R4 single-counter barrier (empirically best: R5 flags +833us, R6 tree +595us)
__device__ __forceinline__ void gridbar() {
    __syncthreads();
    if (threadIdx.x == 0) {
        unsigned my = g_gen;
        __threadfence();
        if (atomicAdd(&g_count, 1u) == RNCTA - 1) {
            g_count = 0u;
            __threadfence();
            g_gen = my + 1u;
        } else {
            while (g_gen == my) { }
        }
    }
    __syncthreads();
}

__global__ void __launch_bounds__(RTPB, 1) recurrent_kernel(
    const float* __restrict__ w_bb, const float* __restrict__ b_bb)
{
    __shared__ float sV[Bb * Nn];          // 32 KB state staging
    __shared__ float sRed[4][16][33];

    const int tid   = threadIdx.x;
    const int lane  = tid & 31;
    const int warp  = tid >> 5;
    const int jbase = blockIdx.x * 8;
    const int j0    = jbase + warp * 2;

    float wreg[8][4][2];
#pragma unroll
    for (int i = 0; i < 8; i++) {
#pragma unroll
        for (int d = 0; d < 4; d++) {
            int k = 4 * lane + 128 * i + d;
            wreg[i][d][0] = w_bb[k * Nn + j0];
            wreg[i][d][1] = w_bb[k * Nn + j0 + 1];
        }
    }
    const float bias0 = b_bb[j0];
    const float bias1 = b_bb[j0 + 1];

    const uint32_t sV32 = smem_u32(sV);

    if (tid < 64) {
        int b = tid >> 3, c = tid & 7;
        g_S[0][b * Nn + jbase + c] = 0.f;
    }
    gridbar();

    int cur = 0;
#pragma unroll 1
    for (int t = 0; t < Tt; t++) {
#pragma unroll 1
        for (int step = 0; step < 4; step++) {
            const float4* src = (const float4*)&g_S[cur][0];
            float acc[16];
#pragma unroll
            for (int o = 0; o < 16; o++) acc[o] = 0.f;

            if (step == 0) {
                // register path: add x_t while staging
                const float4* xs = (const float4*)g_X;
                for (int r = tid; r < (Bb * Nn) / 4; r += RTPB) {
                    float4 a = __ldcg(src + r);
                    int b  = r >> 8;
                    int k4 = r & 255;
                    float4 x = xs[(b * Tt + t) * (Nn / 4) + k4];
                    a.x += x.x; a.y += x.y; a.z += x.z; a.w += x.w;
                    ((float4*)sV)[r] = a;
                }
                __syncthreads();
#pragma unroll
                for (int i = 0; i < 8; i++) {
#pragma unroll
                    for (int b = 0; b < Bb; b++) {
                        float4 v = *(const float4*)&sV[b * Nn + 4 * lane + 128 * i];
                        acc[b*2+0] = fmaf(v.x, wreg[i][0][0], acc[b*2+0]);
                        acc[b*2+0] = fmaf(v.y, wreg[i][1][0], acc[b*2+0]);
                        acc[b*2+0] = fmaf(v.z, wreg[i][2][0], acc[b*2+0]);
                        acc[b*2+0] = fmaf(v.w, wreg[i][3][0], acc[b*2+0]);
                        acc[b*2+1] = fmaf(v.x, wreg[i][0][1], acc[b*2+1]);
                        acc[b*2+1] = fmaf(v.y, wreg[i][1][1], acc[b*2+1]);
                        acc[b*2+1] = fmaf(v.z, wreg[i][2][1], acc[b*2+1]);
                        acc[b*2+1] = fmaf(v.w, wreg[i][3][1], acc[b*2+1]);
                    }
                }
            } else {
                // cp.async path: half0 (batches 0..3) then half1 (4..7), overlapped
#pragma unroll
                for (int k = 0; k < 8; k++) {
                    int r = tid + k * RTPB;           // 0..1023
                    cp16(sV32 + r * 16, src + r);
                }
                cp_commit();
#pragma unroll
                for (int k = 8; k < 16; k++) {
                    int r = tid + k * RTPB;           // 1024..2047
                    cp16(sV32 + r * 16, src + r);
                }
                cp_commit();

                cp_wait<1>();
                __syncthreads();
#pragma unroll
                for (int i = 0; i < 8; i++) {
#pragma unroll
                    for (int b = 0; b < 4; b++) {
                        float4 v = *(const float4*)&sV[b * Nn + 4 * lane + 128 * i];
                        acc[b*2+0] = fmaf(v.x, wreg[i][0][0], acc[b*2+0]);
                        acc[b*2+0] = fmaf(v.y, wreg[i][1][0], acc[b*2+0]);
                        acc[b*2+0] = fmaf(v.z, wreg[i][2][0], acc[b*2+0]);
                        acc[b*2+0] = fmaf(v.w, wreg[i][3][0], acc[b*2+0]);
                        acc[b*2+1] = fmaf(v.x, wreg[i][0][1], acc[b*2+1]);
                        acc[b*2+1] = fmaf(v.y, wreg[i][1][1], acc[b*2+1]);
                        acc[b*2+1] = fmaf(v.z, wreg[i][2][1], acc[b*2+1]);
                        acc[b*2+1] = fmaf(v.w, wreg[i][3][1], acc[b*2+1]);
                    }
                }
                cp_wait<0>();
                __syncthreads();
#pragma unroll
                for (int i = 0; i < 8; i++) {
#pragma unroll
                    for (int b = 4; b < 8; b++) {
                        float4 v = *(const float4*)&sV[b * Nn + 4 * lane + 128 * i];
                        acc[b*2+0] = fmaf(v.x, wreg[i][0][0], acc[b*2+0]);
                        acc[b*2+0] = fmaf(v.y, wreg[i][1][0], acc[b*2+0]);
                        acc[b*2+0] = fmaf(v.z, wreg[i][2][0], acc[b*2+0]);
                        acc[b*2+0] = fmaf(v.w, wreg[i][3][0], acc[b*2+0]);
                        acc[b*2+1] = fmaf(v.x, wreg[i][0][1], acc[b*2+1]);
                        acc[b*2+1] = fmaf(v.y, wreg[i][1][1], acc[b*2+1]);
                        acc[b*2+1] = fmaf(v.z, wreg[i][2][1], acc[b*2+1]);
                        acc[b*2+1] = fmaf(v.w, wreg[i][3][1], acc[b*2+1]);
                    }
                }
            }

            // staging + 2-lane-per-output reduction (all 32 lanes active)
#pragma unroll
            for (int o = 0; o < 16; o++) sRed[warp][o][lane] = acc[o];
            __syncwarp();

            const int nxt = cur ^ 1;
            {
                const int o = lane >> 1;
                const int h = lane & 1;
                float s = 0.f;
#pragma unroll
                for (int l = 0; l < 16; l++) s += sRed[warp][o][h * 16 + l];
                s += __shfl_xor_sync(0xffffffffu, s, 1);
                if (h == 0) {
                    int b = o >> 1, j = o & 1;
                    s += (j ? bias1 : bias0);
                    float sn = tanhf(s);
                    g_S[nxt][b * Nn + j0 + j] = sn;
                    if (step == 3) g_H[(b * Tt + t) * Nn + j0 + j] = sn;
                }
            }
            cur ^= 1;
            gridbar();
        }
    }
}

// ---------------- layernorm ----------------
__global__ void __launch_bounds__(256) ln_kernel(
    const float* __restrict__ in, float* __restrict__ outp,
    const float* __restrict__ gamma, const float* __restrict__ beta)
{
    const int row = blockIdx.x;
    const int tid = threadIdx.x;
    float4 v = ((const float4*)(in + row * Nn))[tid];
    float s = v.x + v.y + v.z + v.w;
    float q = v.x*v.x + v.y*v.y + v.z*v.z + v.w*v.w;
#pragma unroll
    for (int off = 16; off; off >>= 1) {
        s += __shfl_xor_sync(0xffffffffu, s, off);
        q += __shfl_xor_sync(0xffffffffu, q, off);
    }
    __shared__ float rs[8], rq[8];
    int lane = tid & 31, w = tid >> 5;
    if (lane == 0) { rs[w] = s; rq[w] = q; }
    __syncthreads();
    float ts = 0.f, tq = 0.f;
#pragma unroll
    for (int i = 0; i < 8; i++) { ts += rs[i]; tq += rq[i]; }
    float m   = ts * (1.f / Nn);
    float var = tq * (1.f / Nn) - m * m;
    float r   = rsqrtf(var + 1e-5f);
    float4 g  = ((const float4*)gamma)[tid];
    float4 be = ((const float4*)beta)[tid];
    float4 o;
    o.x = (v.x - m) * r * g.x + be.x;
    o.y = (v.y - m) * r * g.y + be.y;
    o.z = (v.z - m) * r * g.z + be.z;
    o.w = (v.w - m) * r * g.w + be.w;
    ((float4*)(outp + row * Nn))[tid] = o;
}

// ---------------- tiled fp32 GEMM (phases A and C) ----------------
template <bool GATHER, bool BIAS>
__global__ void __launch_bounds__(256) sgemm128(
    int M, int N, int K,
    const float* __restrict__ A, const float* __restrict__ Bm, float* __restrict__ C,
    const int* __restrict__ ids, const float* __restrict__ bias)
{
    constexpr int BM = 128, BN = 128, BK = 8;
    __shared__ float As[BK][BM];
    __shared__ float Bs[BK][BN];

    const int tid = threadIdx.x;
    const int bm  = blockIdx.y * BM;
    const int bn  = blockIdx.x * BN;

    const int innerRowA = tid >> 1;
    const int innerColA = (tid & 1) * 4;
    const int innerRowB = tid >> 5;
    const int innerColB = (tid & 31) * 4;

    const int tr = tid >> 4;
    const int tc = tid & 15;

    const int arow = bm + innerRowA;
    const int arowBase = (GATHER ? ids[arow] : arow) * K;

    float acc[8][8];
#pragma unroll
    for (int i = 0; i < 8; i++)
#pragma unroll
        for (int j = 0; j < 8; j++) acc[i][j] = 0.f;

    for (int kb = 0; kb < K; kb += BK) {
        float4 a = *(const float4*)(A + arowBase + kb + innerColA);
        float4 b = *(const float4*)(Bm + (kb + innerRowB) * N + bn + innerColB);
        As[innerColA + 0][innerRowA] = a.x;
        As[innerColA + 1][innerRowA] = a.y;
        As[innerColA + 2][innerRowA] = a.z;
        As[innerColA + 3][innerRowA] = a.w;
        *(float4*)&Bs[innerRowB][innerColB] = b;
        __syncthreads();

#pragma unroll
        for (int k = 0; k < BK; k++) {
            float rm[8], rn[8];
#pragma unroll
            for (int i = 0; i < 8; i++) rm[i] = As[k][tr * 8 + i];
#pragma unroll
            for (int j = 0; j < 8; j++) rn[j] = Bs[k][tc * 8 + j];
#pragma unroll
            for (int i = 0; i < 8; i++)
#pragma unroll
                for (int j = 0; j < 8; j++)
                    acc[i][j] = fmaf(rm[i], rn[j], acc[i][j]);
        }
        __syncthreads();
    }

#pragma unroll
    for (int i = 0; i < 8; i++) {
        int crow = (bm + tr * 8 + i) * N + bn + tc * 8;
#pragma unroll
        for (int j4 = 0; j4 < 2; j4++) {
            float4 v;
            v.x = acc[i][j4*4+0]; v.y = acc[i][j4*4+1];
            v.z = acc[i][j4*4+2]; v.w = acc[i][j4*4+3];
            if (BIAS) {
                float4 bb = *(const float4*)(bias + bn + tc * 8 + j4 * 4);
                v.x += bb.x; v.y += bb.y; v.z += bb.z; v.w += bb.w;
            }
            *(float4*)(C + crow + j4 * 4) = v;
        }
    }
}

// ---------------- fp32 -> split-bf16 conversions ----------------
__global__ void __launch_bounds__(256) convert_split_kernel(
    const float* __restrict__ src, __nv_bfloat16* __restrict__ hi,
    __nv_bfloat16* __restrict__ lo, int n)
{
    int i = blockIdx.x * blockDim.x + threadIdx.x;
    if (i < n) {
        float x = src[i];
        __nv_bfloat16 h = __float2bfloat16_rn(x);
        hi[i] = h;
        lo[i] = __float2bfloat16_rn(x - __bfloat162float(h));
    }
}

// transpose w_head [E=768, V=32000] -> [V, E] with hi/lo split
__global__ void __launch_bounds__(256) transpose_split_kernel(
    const float* __restrict__ src, __nv_bfloat16* __restrict__ hi,
    __nv_bfloat16* __restrict__ lo)
{
    __shared__ float tile[32][33];
    const int n0 = blockIdx.x * 32;
    const int k0 = blockIdx.y * 32;
    const int tx = threadIdx.x;
    const int ty = threadIdx.y;
#pragma unroll
    for (int j = 0; j < 32; j += 8)
        tile[ty + j][tx] = src[(size_t)(k0 + ty + j) * Vv + n0 + tx];
    __syncthreads();
#pragma unroll
    for (int j = 0; j < 32; j += 8) {
        float x = tile[tx][ty + j];
        __nv_bfloat16 h = __float2bfloat16_rn(x);
        size_t o = (size_t)(n0 + ty + j) * Ee + k0 + tx;
        hi[o] = h;
        lo[o] = __float2bfloat16_rn(x - __bfloat162float(h));
    }
}

// ---------------- HMMA head GEMM: out[2048,32000] = P @ w_head ----------------
constexpr int HSTR = 40;   // smem row stride in bf16 (conflict-free fragment loads)

__device__ __forceinline__ uint32_t lds32(const __nv_bfloat16* p) {
    return *(const uint32_t*)p;
}
__device__ __forceinline__ void mma16816(float* c, const uint32_t* a,
                                         uint32_t b0, uint32_t b1) {
    asm volatile(
        "mma.sync.aligned.m16n8k16.row.col.f32.bf16.bf16.f32 "
        "{%0,%1,%2,%3}, {%4,%5,%6,%7}, {%8,%9}, {%0,%1,%2,%3};"
        : "+f"(c[0]), "+f"(c[1]), "+f"(c[2]), "+f"(c[3])
        : "r"(a[0]), "r"(a[1]), "r"(a[2]), "r"(a[3]), "r"(b0), "r"(b1));
}

__global__ void __launch_bounds__(256) head_mma_kernel(
    const __nv_bfloat16* __restrict__ Ahi, const __nv_bfloat16* __restrict__ Alo,
    const __nv_bfloat16* __restrict__ Bhi, const __nv_bfloat16* __restrict__ Blo,
    float* __restrict__ out)
{
    __shared__ __nv_bfloat16 sAh[128 * HSTR];
    __shared__ __nv_bfloat16 sAl[128 * HSTR];
    __shared__ __nv_bfloat16 sBh[128 * HSTR];
    __shared__ __nv_bfloat16 sBl[128 * HSTR];

    const int tid  = threadIdx.x;
    const int warp = tid >> 5;
    const int lane = tid & 31;
    const int m0 = blockIdx.y * 128;
    const int n0 = blockIdx.x * 128;
    const int wm = (warp >> 1) * 32;
    const int wn = (warp & 1) * 64;
    const int g  = lane >> 2;
    const int t  = lane & 3;

    float c[2][8][4];
#pragma unroll
    for (int i = 0; i < 2; i++)
#pragma unroll
        for (int j = 0; j < 8; j++)
#pragma unroll
            for (int q = 0; q < 4; q++) c[i][j][q] = 0.f;

    const int lr = tid >> 1;
    const int lc = (tid & 1) * 16;
    const __nv_bfloat16* gAh = Ahi + (size_t)(m0 + lr) * Ee + lc;
    const __nv_bfloat16* gAl = Alo + (size_t)(m0 + lr) * Ee + lc;
    const __nv_bfloat16* gBh = Bhi + (size_t)(n0 + lr) * Ee + lc;
    const __nv_bfloat16* gBl = Blo + (size_t)(n0 + lr) * Ee + lc;
    __nv_bfloat16* stA_h = &sAh[lr * HSTR + lc];
    __nv_bfloat16* stA_l = &sAl[lr * HSTR + lc];
    __nv_bfloat16* stB_h = &sBh[lr * HSTR + lc];
    __nv_bfloat16* stB_l = &sBl[lr * HSTR + lc];

#pragma unroll 1
    for (int kb = 0; kb < Ee; kb += 32) {
        *(uint4*)(stA_h)     = *(const uint4*)(gAh + kb);
        *(uint4*)(stA_h + 8) = *(const uint4*)(gAh + kb + 8);
        *(uint4*)(stA_l)     = *(const uint4*)(gAl + kb);
        *(uint4*)(stA_l + 8) = *(const uint4*)(gAl + kb + 8);
        *(uint4*)(stB_h)     = *(const uint4*)(gBh + kb);
        *(uint4*)(stB_h + 8) = *(const uint4*)(gBh + kb + 8);
        *(uint4*)(stB_l)     = *(const uint4*)(gBl + kb);
        *(uint4*)(stB_l + 8) = *(const uint4*)(gBl + kb + 8);
        __syncthreads();

#pragma unroll
        for (int kk = 0; kk < 32; kk += 16) {
            uint32_t ah[2][4], al[2][4];
#pragma unroll
            for (int i = 0; i < 2; i++) {
                int r0 = (wm + 16 * i + g) * HSTR + kk + 2 * t;
                int r1 = (wm + 16 * i + g + 8) * HSTR + kk + 2 * t;
                ah[i][0] = lds32(&sAh[r0]);
                ah[i][1] = lds32(&sAh[r1]);
                ah[i][2] = lds32(&sAh[r0 + 8]);
                ah[i][3] = lds32(&sAh[r1 + 8]);
                al[i][0] = lds32(&sAl[r0]);
                al[i][1] = lds32(&sAl[r1]);
                al[i][2] = lds32(&sAl[r0 + 8]);
                al[i][3] = lds32(&sAl[r1 + 8]);
            }
#pragma unroll
            for (int j = 0; j < 8; j++) {
                int nb = (wn + 8 * j + g) * HSTR + kk + 2 * t;
                uint32_t bh0 = lds32(&sBh[nb]);
                uint32_t bh1 = lds32(&sBh[nb + 8]);
                uint32_t bl0 = lds32(&sBl[nb]);
                uint32_t bl1 = lds32(&sBl[nb + 8]);
#pragma unroll
                for (int i = 0; i < 2; i++) {
                    mma16816(c[i][j], ah[i], bh0, bh1);
                    mma16816(c[i][j], ah[i], bl0, bl1);
                    mma16816(c[i][j], al[i], bh0, bh1);
                }
            }
        }
        __syncthreads();
    }

#pragma unroll
    for (int i = 0; i < 2; i++) {
#pragma unroll
        for (int j = 0; j < 8; j++) {
            int row = m0 + wm + 16 * i + g;
            int col = n0 + wn + 8 * j + 2 * t;
            float2 v0 = make_float2(c[i][j][0], c[i][j][1]);
            float2 v1 = make_float2(c[i][j][2], c[i][j][3]);
            *(float2*)(out + (size_t)row * Vv + col)       = v0;
            *(float2*)(out + (size_t)(row + 8) * Vv + col) = v1;
        }
    }
}

// ---------------- launch ----------------
extern "C" void kernel_launch(void* const* d_in, const int* in_sizes, int n_in,
                              void* d_out, int out_size)
{
    const int*   ids    = (const int*)  d_in[0];
    const float* emb    = (const float*)d_in[1];
    const float* w_in   = (const float*)d_in[2];
    const float* b_in   = (const float*)d_in[3];
    const float* w_bb   = (const float*)d_in[4];
    const float* b_bb   = (const float*)d_in[5];
    const float* gamma  = (const float*)d_in[6];
    const float* beta   = (const float*)d_in[7];
    const float* w_out  = (const float*)d_in[8];
    const float* w_head = (const float*)d_in[9];
    float* out = (float*)d_out;

    float *pX = nullptr, *pH = nullptr, *pHn = nullptr, *pP = nullptr;
    __nv_bfloat16 *pAhi = nullptr, *pAlo = nullptr, *pBhi = nullptr, *pBlo = nullptr;
    cudaGetSymbolAddress((void**)&pX,   g_X);
    cudaGetSymbolAddress((void**)&pH,   g_H);
    cudaGetSymbolAddress((void**)&pHn,  g_Hn);
    cudaGetSymbolAddress((void**)&pP,   g_P);
    cudaGetSymbolAddress((void**)&pAhi, g_Ahi);
    cudaGetSymbolAddress((void**)&pAlo, g_Alo);
    cudaGetSymbolAddress((void**)&pBhi, g_Bhi);
    cudaGetSymbolAddress((void**)&pBlo, g_Blo);

    // 0. reset barrier state (device globals persist across graph replays)
    init_barrier_kernel<<<1, 1>>>();

    // 0b. transpose + split w_head
    {
        dim3 g(Vv / 32, Ee / 32), b(32, 8);
        transpose_split_kernel<<<g, b>>>(w_head, pBhi, pBlo);
    }

    // 1. X = emb[ids] @ w_in + b_in
    {
        dim3 g(Nn / 128, BT / 128);
        sgemm128<true, true><<<g, 256>>>(BT, Nn, Ee, emb, w_in, pX, ids, b_in);
    }

    // 2. recurrent scan (R4 barrier + cp.async-overlapped interior)
    recurrent_kernel<<<RNCTA, RTPB>>>(w_bb, b_bb);

    // 3. layernorm
    ln_kernel<<<BT, 256>>>(pH, pHn, gamma, beta);

    // 4. P = Hn @ w_out
    {
        dim3 g(Ee / 128, BT / 128);
        sgemm128<false, false><<<g, 256>>>(BT, Ee, Nn, pHn, w_out, pP, nullptr, nullptr);
    }

    // 5. split P into bf16 hi/lo
    convert_split_kernel<<<(BT * Ee + 255) / 256, 256>>>(pP, pAhi, pAlo, BT * Ee);

    // 6. logits = P @ w_head via HMMA split-bf16
    {
        dim3 g(Vv / 128, BT / 128);
        head_mma_kernel<<<g, 256>>>(pAhi, pAlo, pBhi, pBlo, out);
    }
}

// round 8
// speedup vs baseline: 1.2868x; 1.0299x over previous
#include <cuda_runtime.h>
#include <cuda_bf16.h>
#include <math.h>
#include <stdint.h>

// Problem constants
constexpr int Bb  = 8;
constexpr int Tt  = 256;
constexpr int Ee  = 768;
constexpr int Nn  = 1024;
constexpr int Vv  = 32000;
constexpr int BT  = Bb * Tt;   // 2048

// ---------------- device scratch (no allocations allowed) ----------------
__device__ float g_X [BT * Nn];
__device__ float g_S [2][Bb * Nn];
__device__ float g_H [BT * Nn];
__device__ float g_Hn[BT * Nn];
__device__ float g_P [BT * Ee];
__device__ __nv_bfloat16 g_Ahi[BT * Ee];
__device__ __nv_bfloat16 g_Alo[BT * Ee];
__device__ __nv_bfloat16 g_Bhi[(size_t)Vv * Ee];  // w_head transposed [V][E]
__device__ __nv_bfloat16 g_Blo[(size_t)Vv * Ee];
__device__ unsigned g_count;
__device__ volatile unsigned g_gen;

__global__ void init_barrier_kernel() {
    g_count = 0u;
    g_gen   = 0u;
}

// ---------------- cp.async helpers ----------------
__device__ __forceinline__ uint32_t smem_u32(const void* p) {
    uint32_t a;
    asm("{ .reg .u64 t; cvta.to.shared.u64 t, %1; cvt.u32.u64 %0, t; }" : "=r"(a) : "l"(p));
    return a;
}
__device__ __forceinline__ void cp16(uint32_t dst, const void* src) {
    asm volatile("cp.async.cg.shared.global [%0], [%1], 16;" :: "r"(dst), "l"(src));
}
__device__ __forceinline__ void cp_commit() {
    asm volatile("cp.async.commit_group;" ::: "memory");
}
template<int N>
__device__ __forceinline__ void cp_wait() {
    asm volatile("cp.async.wait_group %0;" :: "n"(N) : "memory");
}

// ---------------- persistent recurrent kernel ----------------
constexpr int RNCTA = 128;
constexpr int RTPB  = 128;

// R4 single-counter barrier (empirically best: R5 flags +833us, R6 tree +595us)
__device__ __forceinline__ void gridbar() {
    __syncthreads();
    if (threadIdx.x == 0) {
        unsigned my = g_gen;
        __threadfence();
        if (atomicAdd(&g_count, 1u) == RNCTA - 1) {
            g_count = 0u;
            __threadfence();
            g_gen = my + 1u;
        } else {
            while (g_gen == my) { }
        }
    }
    __syncthreads();
}

__global__ void __launch_bounds__(RTPB, 1) recurrent_kernel(
    const float* __restrict__ w_bb, const float* __restrict__ b_bb)
{
    __shared__ float sV[Bb * Nn];          // 32 KB state staging
    __shared__ float sRed[4][16][33];

    const int tid   = threadIdx.x;
    const int lane  = tid & 31;
    const int warp  = tid >> 5;
    const int jbase = blockIdx.x * 8;
    const int j0    = jbase + warp * 2;

    float wreg[8][4][2];
#pragma unroll
    for (int i = 0; i < 8; i++) {
#pragma unroll
        for (int d = 0; d < 4; d++) {
            int k = 4 * lane + 128 * i + d;
            wreg[i][d][0] = w_bb[k * Nn + j0];
            wreg[i][d][1] = w_bb[k * Nn + j0 + 1];
        }
    }
    const float bias0 = b_bb[j0];
    const float bias1 = b_bb[j0 + 1];

    const uint32_t sV32 = smem_u32(sV);

    if (tid < 64) {
        int b = tid >> 3, c = tid & 7;
        g_S[0][b * Nn + jbase + c] = 0.f;
    }
    gridbar();

    int cur = 0;
#pragma unroll 1
    for (int t = 0; t < Tt; t++) {
#pragma unroll 1
        for (int step = 0; step < 4; step++) {
            const float4* src = (const float4*)&g_S[cur][0];
            float acc[16];
#pragma unroll
            for (int o = 0; o < 16; o++) acc[o] = 0.f;

            if (step == 0) {
                // register path: add x_t while staging
                const float4* xs = (const float4*)g_X;
                for (int r = tid; r < (Bb * Nn) / 4; r += RTPB) {
                    float4 a = __ldcg(src + r);
                    int b  = r >> 8;
                    int k4 = r & 255;
                    float4 x = xs[(b * Tt + t) * (Nn / 4) + k4];
                    a.x += x.x; a.y += x.y; a.z += x.z; a.w += x.w;
                    ((float4*)sV)[r] = a;
                }
                __syncthreads();
#pragma unroll
                for (int i = 0; i < 8; i++) {
#pragma unroll
                    for (int b = 0; b < Bb; b++) {
                        float4 v = *(const float4*)&sV[b * Nn + 4 * lane + 128 * i];
                        acc[b*2+0] = fmaf(v.x, wreg[i][0][0], acc[b*2+0]);
                        acc[b*2+0] = fmaf(v.y, wreg[i][1][0], acc[b*2+0]);
                        acc[b*2+0] = fmaf(v.z, wreg[i][2][0], acc[b*2+0]);
                        acc[b*2+0] = fmaf(v.w, wreg[i][3][0], acc[b*2+0]);
                        acc[b*2+1] = fmaf(v.x, wreg[i][0][1], acc[b*2+1]);
                        acc[b*2+1] = fmaf(v.y, wreg[i][1][1], acc[b*2+1]);
                        acc[b*2+1] = fmaf(v.z, wreg[i][2][1], acc[b*2+1]);
                        acc[b*2+1] = fmaf(v.w, wreg[i][3][1], acc[b*2+1]);
                    }
                }
            } else {
                // cp.async path: half0 (batches 0..3) then half1 (4..7), overlapped
#pragma unroll
                for (int k = 0; k < 8; k++) {
                    int r = tid + k * RTPB;           // 0..1023
                    cp16(sV32 + r * 16, src + r);
                }
                cp_commit();
#pragma unroll
                for (int k = 8; k < 16; k++) {
                    int r = tid + k * RTPB;           // 1024..2047
                    cp16(sV32 + r * 16, src + r);
                }
                cp_commit();

                cp_wait<1>();
                __syncthreads();
#pragma unroll
                for (int i = 0; i < 8; i++) {
#pragma unroll
                    for (int b = 0; b < 4; b++) {
                        float4 v = *(const float4*)&sV[b * Nn + 4 * lane + 128 * i];
                        acc[b*2+0] = fmaf(v.x, wreg[i][0][0], acc[b*2+0]);
                        acc[b*2+0] = fmaf(v.y, wreg[i][1][0], acc[b*2+0]);
                        acc[b*2+0] = fmaf(v.z, wreg[i][2][0], acc[b*2+0]);
                        acc[b*2+0] = fmaf(v.w, wreg[i][3][0], acc[b*2+0]);
                        acc[b*2+1] = fmaf(v.x, wreg[i][0][1], acc[b*2+1]);
                        acc[b*2+1] = fmaf(v.y, wreg[i][1][1], acc[b*2+1]);
                        acc[b*2+1] = fmaf(v.z, wreg[i][2][1], acc[b*2+1]);
                        acc[b*2+1] = fmaf(v.w, wreg[i][3][1], acc[b*2+1]);
                    }
                }
                cp_wait<0>();
                __syncthreads();
#pragma unroll
                for (int i = 0; i < 8; i++) {
#pragma unroll
                    for (int b = 4; b < 8; b++) {
                        float4 v = *(const float4*)&sV[b * Nn + 4 * lane + 128 * i];
                        acc[b*2+0] = fmaf(v.x, wreg[i][0][0], acc[b*2+0]);
                        acc[b*2+0] = fmaf(v.y, wreg[i][1][0], acc[b*2+0]);
                        acc[b*2+0] = fmaf(v.z, wreg[i][2][0], acc[b*2+0]);
                        acc[b*2+0] = fmaf(v.w, wreg[i][3][0], acc[b*2+0]);
                        acc[b*2+1] = fmaf(v.x, wreg[i][0][1], acc[b*2+1]);
                        acc[b*2+1] = fmaf(v.y, wreg[i][1][1], acc[b*2+1]);
                        acc[b*2+1] = fmaf(v.z, wreg[i][2][1], acc[b*2+1]);
                        acc[b*2+1] = fmaf(v.w, wreg[i][3][1], acc[b*2+1]);
                    }
                }
            }

            // staging + 2-lane-per-output reduction (all 32 lanes active)
#pragma unroll
            for (int o = 0; o < 16; o++) sRed[warp][o][lane] = acc[o];
            __syncwarp();

            const int nxt = cur ^ 1;
            {
                const int o = lane >> 1;
                const int h = lane & 1;
                float s = 0.f;
#pragma unroll
                for (int l = 0; l < 16; l++) s += sRed[warp][o][h * 16 + l];
                s += __shfl_xor_sync(0xffffffffu, s, 1);
                if (h == 0) {
                    int b = o >> 1, j = o & 1;
                    s += (j ? bias1 : bias0);
                    float sn = tanhf(s);
                    g_S[nxt][b * Nn + j0 + j] = sn;
                    if (step == 3) g_H[(b * Tt + t) * Nn + j0 + j] = sn;
                }
            }
            cur ^= 1;
            gridbar();
        }
    }
}

// ---------------- layernorm ----------------
__global__ void __launch_bounds__(256) ln_kernel(
    const float* __restrict__ in, float* __restrict__ outp,
    const float* __restrict__ gamma, const float* __restrict__ beta)
{
    const int row = blockIdx.x;
    const int tid = threadIdx.x;
    float4 v = ((const float4*)(in + row * Nn))[tid];
    float s = v.x + v.y + v.z + v.w;
    float q = v.x*v.x + v.y*v.y + v.z*v.z + v.w*v.w;
#pragma unroll
    for (int off = 16; off; off >>= 1) {
        s += __shfl_xor_sync(0xffffffffu, s, off);
        q += __shfl_xor_sync(0xffffffffu, q, off);
    }
    __shared__ float rs[8], rq[8];
    int lane = tid & 31, w = tid >> 5;
    if (lane == 0) { rs[w] = s; rq[w] = q; }
    __syncthreads();
    float ts = 0.f, tq = 0.f;
#pragma unroll
    for (int i = 0; i < 8; i++) { ts += rs[i]; tq += rq[i]; }
    float m   = ts * (1.f / Nn);
    float var = tq * (1.f / Nn) - m * m;
    float r   = rsqrtf(var + 1e-5f);
    float4 g  = ((const float4*)gamma)[tid];
    float4 be = ((const float4*)beta)[tid];
    float4 o;
    o.x = (v.x - m) * r * g.x + be.x;
    o.y = (v.y - m) * r * g.y + be.y;
    o.z = (v.z - m) * r * g.z + be.z;
    o.w = (v.w - m) * r * g.w + be.w;
    ((float4*)(outp + row * Nn))[tid] = o;
}

// ---------------- tiled fp32 GEMM (phases A and C) ----------------
template <bool GATHER, bool BIAS>
__global__ void __launch_bounds__(256) sgemm128(
    int M, int N, int K,
    const float* __restrict__ A, const float* __restrict__ Bm, float* __restrict__ C,
    const int* __restrict__ ids, const float* __restrict__ bias)
{
    constexpr int BM = 128, BN = 128, BK = 8;
    __shared__ float As[BK][BM];
    __shared__ float Bs[BK][BN];

    const int tid = threadIdx.x;
    const int bm  = blockIdx.y * BM;
    const int bn  = blockIdx.x * BN;

    const int innerRowA = tid >> 1;
    const int innerColA = (tid & 1) * 4;
    const int innerRowB = tid >> 5;
    const int innerColB = (tid & 31) * 4;

    const int tr = tid >> 4;
    const int tc = tid & 15;

    const int arow = bm + innerRowA;
    const int arowBase = (GATHER ? ids[arow] : arow) * K;

    float acc[8][8];
#pragma unroll
    for (int i = 0; i < 8; i++)
#pragma unroll
        for (int j = 0; j < 8; j++) acc[i][j] = 0.f;

    for (int kb = 0; kb < K; kb += BK) {
        float4 a = *(const float4*)(A + arowBase + kb + innerColA);
        float4 b = *(const float4*)(Bm + (kb + innerRowB) * N + bn + innerColB);
        As[innerColA + 0][innerRowA] = a.x;
        As[innerColA + 1][innerRowA] = a.y;
        As[innerColA + 2][innerRowA] = a.z;
        As[innerColA + 3][innerRowA] = a.w;
        *(float4*)&Bs[innerRowB][innerColB] = b;
        __syncthreads();

#pragma unroll
        for (int k = 0; k < BK; k++) {
            float rm[8], rn[8];
#pragma unroll
            for (int i = 0; i < 8; i++) rm[i] = As[k][tr * 8 + i];
#pragma unroll
            for (int j = 0; j < 8; j++) rn[j] = Bs[k][tc * 8 + j];
#pragma unroll
            for (int i = 0; i < 8; i++)
#pragma unroll
                for (int j = 0; j < 8; j++)
                    acc[i][j] = fmaf(rm[i], rn[j], acc[i][j]);
        }
        __syncthreads();
    }

#pragma unroll
    for (int i = 0; i < 8; i++) {
        int crow = (bm + tr * 8 + i) * N + bn + tc * 8;
#pragma unroll
        for (int j4 = 0; j4 < 2; j4++) {
            float4 v;
            v.x = acc[i][j4*4+0]; v.y = acc[i][j4*4+1];
            v.z = acc[i][j4*4+2]; v.w = acc[i][j4*4+3];
            if (BIAS) {
                float4 bb = *(const float4*)(bias + bn + tc * 8 + j4 * 4);
                v.x += bb.x; v.y += bb.y; v.z += bb.z; v.w += bb.w;
            }
            *(float4*)(C + crow + j4 * 4) = v;
        }
    }
}

// ---------------- fp32 -> split-bf16 conversions ----------------
__global__ void __launch_bounds__(256) convert_split_kernel(
    const float* __restrict__ src, __nv_bfloat16* __restrict__ hi,
    __nv_bfloat16* __restrict__ lo, int n)
{
    int i = blockIdx.x * blockDim.x + threadIdx.x;
    if (i < n) {
        float x = src[i];
        __nv_bfloat16 h = __float2bfloat16_rn(x);
        hi[i] = h;
        lo[i] = __float2bfloat16_rn(x - __bfloat162float(h));
    }
}

// transpose w_head [E=768, V=32000] -> [V, E] with hi/lo split
__global__ void __launch_bounds__(256) transpose_split_kernel(
    const float* __restrict__ src, __nv_bfloat16* __restrict__ hi,
    __nv_bfloat16* __restrict__ lo)
{
    __shared__ float tile[32][33];
    const int n0 = blockIdx.x * 32;
    const int k0 = blockIdx.y * 32;
    const int tx = threadIdx.x;
    const int ty = threadIdx.y;
#pragma unroll
    for (int j = 0; j < 32; j += 8)
        tile[ty + j][tx] = src[(size_t)(k0 + ty + j) * Vv + n0 + tx];
    __syncthreads();
#pragma unroll
    for (int j = 0; j < 32; j += 8) {
        float x = tile[tx][ty + j];
        __nv_bfloat16 h = __float2bfloat16_rn(x);
        size_t o = (size_t)(n0 + ty + j) * Ee + k0 + tx;
        hi[o] = h;
        lo[o] = __float2bfloat16_rn(x - __bfloat162float(h));
    }
}

// ---------------- HMMA head GEMM (cp.async double-buffered) ----------------
constexpr int HSTR   = 40;                  // smem row stride in bf16
constexpr int HTILE  = 128 * HSTR * 2;      // 10240 B per operand tile
constexpr int HSTAGE = HTILE * 4;           // 40960 B per stage
constexpr int HG_SMEM = HSTAGE * 2;         // 81920 B

__device__ __forceinline__ uint32_t lds32(const __nv_bfloat16* p) {
    return *(const uint32_t*)p;
}
__device__ __forceinline__ void mma16816(float* c, const uint32_t* a,
                                         uint32_t b0, uint32_t b1) {
    asm volatile(
        "mma.sync.aligned.m16n8k16.row.col.f32.bf16.bf16.f32 "
        "{%0,%1,%2,%3}, {%4,%5,%6,%7}, {%8,%9}, {%0,%1,%2,%3};"
        : "+f"(c[0]), "+f"(c[1]), "+f"(c[2]), "+f"(c[3])
        : "r"(a[0]), "r"(a[1]), "r"(a[2]), "r"(a[3]), "r"(b0), "r"(b1));
}

__global__ void __launch_bounds__(256) head_mma_kernel(
    const __nv_bfloat16* __restrict__ Ahi, const __nv_bfloat16* __restrict__ Alo,
    const __nv_bfloat16* __restrict__ Bhi, const __nv_bfloat16* __restrict__ Blo,
    float* __restrict__ out)
{
    extern __shared__ char hsm[];
    const uint32_t sbase = smem_u32(hsm);

    const int tid  = threadIdx.x;
    const int warp = tid >> 5;
    const int lane = tid & 31;
    const int m0 = blockIdx.y * 128;
    const int n0 = blockIdx.x * 128;
    const int wm = (warp >> 1) * 32;
    const int wn = (warp & 1) * 64;
    const int g  = lane >> 2;
    const int t  = lane & 3;

    // loader mapping: each thread owns one (row, 16-col half)
    const int lr = tid >> 1;
    const int lc = (tid & 1) * 16;
    const uint32_t soff = (uint32_t)(lr * HSTR + lc) * 2;
    const __nv_bfloat16* gsrc[4];
    gsrc[0] = Ahi + (size_t)(m0 + lr) * Ee + lc;
    gsrc[1] = Alo + (size_t)(m0 + lr) * Ee + lc;
    gsrc[2] = Bhi + (size_t)(n0 + lr) * Ee + lc;
    gsrc[3] = Blo + (size_t)(n0 + lr) * Ee + lc;

    float c[2][8][4];
#pragma unroll
    for (int i = 0; i < 2; i++)
#pragma unroll
        for (int j = 0; j < 8; j++)
#pragma unroll
            for (int q = 0; q < 4; q++) c[i][j][q] = 0.f;

    // prologue: stage 0
    {
#pragma unroll
        for (int a = 0; a < 4; a++) {
            uint32_t d = sbase + a * HTILE + soff;
            cp16(d, gsrc[a]);
            cp16(d + 16, gsrc[a] + 8);
        }
        cp_commit();
    }

#pragma unroll 1
    for (int it = 0; it < 24; it++) {
        if (it + 1 < 24) {
            const int st = (it + 1) & 1;
            const int kb = (it + 1) * 32;
#pragma unroll
            for (int a = 0; a < 4; a++) {
                uint32_t d = sbase + st * HSTAGE + a * HTILE + soff;
                cp16(d, gsrc[a] + kb);
                cp16(d + 16, gsrc[a] + kb + 8);
            }
            cp_commit();
            cp_wait<1>();
        } else {
            cp_wait<0>();
        }
        __syncthreads();

        const char* stg = hsm + (it & 1) * HSTAGE;
        const __nv_bfloat16* sAh = (const __nv_bfloat16*)(stg);
        const __nv_bfloat16* sAl = (const __nv_bfloat16*)(stg + HTILE);
        const __nv_bfloat16* sBh = (const __nv_bfloat16*)(stg + 2 * HTILE);
        const __nv_bfloat16* sBl = (const __nv_bfloat16*)(stg + 3 * HTILE);

#pragma unroll
        for (int kk = 0; kk < 32; kk += 16) {
            uint32_t ah[2][4], al[2][4];
#pragma unroll
            for (int i = 0; i < 2; i++) {
                int r0 = (wm + 16 * i + g) * HSTR + kk + 2 * t;
                int r1 = (wm + 16 * i + g + 8) * HSTR + kk + 2 * t;
                ah[i][0] = lds32(&sAh[r0]);
                ah[i][1] = lds32(&sAh[r1]);
                ah[i][2] = lds32(&sAh[r0 + 8]);
                ah[i][3] = lds32(&sAh[r1 + 8]);
                al[i][0] = lds32(&sAl[r0]);
                al[i][1] = lds32(&sAl[r1]);
                al[i][2] = lds32(&sAl[r0 + 8]);
                al[i][3] = lds32(&sAl[r1 + 8]);
            }
#pragma unroll
            for (int j = 0; j < 8; j++) {
                int nb = (wn + 8 * j + g) * HSTR + kk + 2 * t;
                uint32_t bh0 = lds32(&sBh[nb]);
                uint32_t bh1 = lds32(&sBh[nb + 8]);
                uint32_t bl0 = lds32(&sBl[nb]);
                uint32_t bl1 = lds32(&sBl[nb + 8]);
#pragma unroll
                for (int i = 0; i < 2; i++) {
                    mma16816(c[i][j], ah[i], bh0, bh1);
                    mma16816(c[i][j], ah[i], bl0, bl1);
                    mma16816(c[i][j], al[i], bh0, bh1);
                }
            }
        }
        __syncthreads();
    }

    // epilogue: direct float2 stores
#pragma unroll
    for (int i = 0; i < 2; i++) {
#pragma unroll
        for (int j = 0; j < 8; j++) {
            int row = m0 + wm + 16 * i + g;
            int col = n0 + wn + 8 * j + 2 * t;
            float2 v0 = make_float2(c[i][j][0], c[i][j][1]);
            float2 v1 = make_float2(c[i][j][2], c[i][j][3]);
            *(float2*)(out + (size_t)row * Vv + col)       = v0;
            *(float2*)(out + (size_t)(row + 8) * Vv + col) = v1;
        }
    }
}

// ---------------- launch ----------------
extern "C" void kernel_launch(void* const* d_in, const int* in_sizes, int n_in,
                              void* d_out, int out_size)
{
    const int*   ids    = (const int*)  d_in[0];
    const float* emb    = (const float*)d_in[1];
    const float* w_in   = (const float*)d_in[2];
    const float* b_in   = (const float*)d_in[3];
    const float* w_bb   = (const float*)d_in[4];
    const float* b_bb   = (const float*)d_in[5];
    const float* gamma  = (const float*)d_in[6];
    const float* beta   = (const float*)d_in[7];
    const float* w_out  = (const float*)d_in[8];
    const float* w_head = (const float*)d_in[9];
    float* out = (float*)d_out;

    float *pX = nullptr, *pH = nullptr, *pHn = nullptr, *pP = nullptr;
    __nv_bfloat16 *pAhi = nullptr, *pAlo = nullptr, *pBhi = nullptr, *pBlo = nullptr;
    cudaGetSymbolAddress((void**)&pX,   g_X);
    cudaGetSymbolAddress((void**)&pH,   g_H);
    cudaGetSymbolAddress((void**)&pHn,  g_Hn);
    cudaGetSymbolAddress((void**)&pP,   g_P);
    cudaGetSymbolAddress((void**)&pAhi, g_Ahi);
    cudaGetSymbolAddress((void**)&pAlo, g_Alo);
    cudaGetSymbolAddress((void**)&pBhi, g_Bhi);
    cudaGetSymbolAddress((void**)&pBlo, g_Blo);

    cudaFuncSetAttribute(head_mma_kernel,
                         cudaFuncAttributeMaxDynamicSharedMemorySize, HG_SMEM);

    // 0. reset barrier state (device globals persist across graph replays)
    init_barrier_kernel<<<1, 1>>>();

    // 0b. transpose + split w_head
    {
        dim3 g(Vv / 32, Ee / 32), b(32, 8);
        transpose_split_kernel<<<g, b>>>(w_head, pBhi, pBlo);
    }

    // 1. X = emb[ids] @ w_in + b_in
    {
        dim3 g(Nn / 128, BT / 128);
        sgemm128<true, true><<<g, 256>>>(BT, Nn, Ee, emb, w_in, pX, ids, b_in);
    }

    // 2. recurrent scan (R4 barrier + cp.async-overlapped interior)
    recurrent_kernel<<<RNCTA, RTPB>>>(w_bb, b_bb);

    // 3. layernorm
    ln_kernel<<<BT, 256>>>(pH, pHn, gamma, beta);

    // 4. P = Hn @ w_out
    {
        dim3 g(Ee / 128, BT / 128);
        sgemm128<false, false><<<g, 256>>>(BT, Ee, Nn, pHn, w_out, pP, nullptr, nullptr);
    }

    // 5. split P into bf16 hi/lo
    convert_split_kernel<<<(BT * Ee + 255) / 256, 256>>>(pP, pAhi, pAlo, BT * Ee);

    // 6. logits = P @ w_head via pipelined HMMA split-bf16
    {
        dim3 g(Vv / 128, BT / 128);
        head_mma_kernel<<<g, 256, HG_SMEM>>>(pAhi, pAlo, pBhi, pBlo, out);
    }
}

// round 9
// speedup vs baseline: 1.3086x; 1.0169x over previous
#include <cuda_runtime.h>
#include <cuda_bf16.h>
#include <math.h>
#include <stdint.h>

// Problem constants
constexpr int Bb  = 8;
constexpr int Tt  = 256;
constexpr int Ee  = 768;
constexpr int Nn  = 1024;
constexpr int Vv  = 32000;
constexpr int BT  = Bb * Tt;   // 2048

// ---------------- device scratch (no allocations allowed) ----------------
__device__ float g_X [BT * Nn];
__device__ float g_S [2][Bb * Nn];
__device__ float g_H [BT * Nn];
__device__ float g_Hn[BT * Nn];
__device__ float g_P [BT * Ee];                 // tf32-rounded before head GEMM
__device__ float g_Bt[(size_t)Vv * Ee];         // w_head transposed [V][E], tf32-rounded
__device__ unsigned g_count;
__device__ volatile unsigned g_gen;

__global__ void init_barrier_kernel() {
    g_count = 0u;
    g_gen   = 0u;
}

// ---------------- helpers ----------------
__device__ __forceinline__ uint32_t smem_u32(const void* p) {
    uint32_t a;
    asm("{ .reg .u64 t; cvta.to.shared.u64 t, %1; cvt.u32.u64 %0, t; }" : "=r"(a) : "l"(p));
    return a;
}
__device__ __forceinline__ void cp16(uint32_t dst, const void* src) {
    asm volatile("cp.async.cg.shared.global [%0], [%1], 16;" :: "r"(dst), "l"(src));
}
__device__ __forceinline__ void cp_commit() {
    asm volatile("cp.async.commit_group;" ::: "memory");
}
template<int N>
__device__ __forceinline__ void cp_wait() {
    asm volatile("cp.async.wait_group %0;" :: "n"(N) : "memory");
}
__device__ __forceinline__ float tf32r(float x) {
    uint32_t r;
    asm("cvt.rna.tf32.f32 %0, %1;" : "=r"(r) : "f"(x));
    return __uint_as_float(r);
}

// ---------------- persistent recurrent kernel (identical to R8) ----------------
constexpr int RNCTA = 128;
constexpr int RTPB  = 128;

__device__ __forceinline__ void gridbar() {
    __syncthreads();
    if (threadIdx.x == 0) {
        unsigned my = g_gen;
        __threadfence();
        if (atomicAdd(&g_count, 1u) == RNCTA - 1) {
            g_count = 0u;
            __threadfence();
            g_gen = my + 1u;
        } else {
            while (g_gen == my) { }
        }
    }
    __syncthreads();
}

__global__ void __launch_bounds__(RTPB, 1) recurrent_kernel(
    const float* __restrict__ w_bb, const float* __restrict__ b_bb)
{
    __shared__ float sV[Bb * Nn];
    __shared__ float sRed[4][16][33];

    const int tid   = threadIdx.x;
    const int lane  = tid & 31;
    const int warp  = tid >> 5;
    const int jbase = blockIdx.x * 8;
    const int j0    = jbase + warp * 2;

    float wreg[8][4][2];
#pragma unroll
    for (int i = 0; i < 8; i++) {
#pragma unroll
        for (int d = 0; d < 4; d++) {
            int k = 4 * lane + 128 * i + d;
            wreg[i][d][0] = w_bb[k * Nn + j0];
            wreg[i][d][1] = w_bb[k * Nn + j0 + 1];
        }
    }
    const float bias0 = b_bb[j0];
    const float bias1 = b_bb[j0 + 1];

    const uint32_t sV32 = smem_u32(sV);

    if (tid < 64) {
        int b = tid >> 3, c = tid & 7;
        g_S[0][b * Nn + jbase + c] = 0.f;
    }
    gridbar();

    int cur = 0;
#pragma unroll 1
    for (int t = 0; t < Tt; t++) {
#pragma unroll 1
        for (int step = 0; step < 4; step++) {
            const float4* src = (const float4*)&g_S[cur][0];
            float acc[16];
#pragma unroll
            for (int o = 0; o < 16; o++) acc[o] = 0.f;

            if (step == 0) {
                const float4* xs = (const float4*)g_X;
                for (int r = tid; r < (Bb * Nn) / 4; r += RTPB) {
                    float4 a = __ldcg(src + r);
                    int b  = r >> 8;
                    int k4 = r & 255;
                    float4 x = xs[(b * Tt + t) * (Nn / 4) + k4];
                    a.x += x.x; a.y += x.y; a.z += x.z; a.w += x.w;
                    ((float4*)sV)[r] = a;
                }
                __syncthreads();
#pragma unroll
                for (int i = 0; i < 8; i++) {
#pragma unroll
                    for (int b = 0; b < Bb; b++) {
                        float4 v = *(const float4*)&sV[b * Nn + 4 * lane + 128 * i];
                        acc[b*2+0] = fmaf(v.x, wreg[i][0][0], acc[b*2+0]);
                        acc[b*2+0] = fmaf(v.y, wreg[i][1][0], acc[b*2+0]);
                        acc[b*2+0] = fmaf(v.z, wreg[i][2][0], acc[b*2+0]);
                        acc[b*2+0] = fmaf(v.w, wreg[i][3][0], acc[b*2+0]);
                        acc[b*2+1] = fmaf(v.x, wreg[i][0][1], acc[b*2+1]);
                        acc[b*2+1] = fmaf(v.y, wreg[i][1][1], acc[b*2+1]);
                        acc[b*2+1] = fmaf(v.z, wreg[i][2][1], acc[b*2+1]);
                        acc[b*2+1] = fmaf(v.w, wreg[i][3][1], acc[b*2+1]);
                    }
                }
            } else {
#pragma unroll
                for (int k = 0; k < 8; k++) {
                    int r = tid + k * RTPB;
                    cp16(sV32 + r * 16, src + r);
                }
                cp_commit();
#pragma unroll
                for (int k = 8; k < 16; k++) {
                    int r = tid + k * RTPB;
                    cp16(sV32 + r * 16, src + r);
                }
                cp_commit();

                cp_wait<1>();
                __syncthreads();
#pragma unroll
                for (int i = 0; i < 8; i++) {
#pragma unroll
                    for (int b = 0; b < 4; b++) {
                        float4 v = *(const float4*)&sV[b * Nn + 4 * lane + 128 * i];
                        acc[b*2+0] = fmaf(v.x, wreg[i][0][0], acc[b*2+0]);
                        acc[b*2+0] = fmaf(v.y, wreg[i][1][0], acc[b*2+0]);
                        acc[b*2+0] = fmaf(v.z, wreg[i][2][0], acc[b*2+0]);
                        acc[b*2+0] = fmaf(v.w, wreg[i][3][0], acc[b*2+0]);
                        acc[b*2+1] = fmaf(v.x, wreg[i][0][1], acc[b*2+1]);
                        acc[b*2+1] = fmaf(v.y, wreg[i][1][1], acc[b*2+1]);
                        acc[b*2+1] = fmaf(v.z, wreg[i][2][1], acc[b*2+1]);
                        acc[b*2+1] = fmaf(v.w, wreg[i][3][1], acc[b*2+1]);
                    }
                }
                cp_wait<0>();
                __syncthreads();
#pragma unroll
                for (int i = 0; i < 8; i++) {
#pragma unroll
                    for (int b = 4; b < 8; b++) {
                        float4 v = *(const float4*)&sV[b * Nn + 4 * lane + 128 * i];
                        acc[b*2+0] = fmaf(v.x, wreg[i][0][0], acc[b*2+0]);
                        acc[b*2+0] = fmaf(v.y, wreg[i][1][0], acc[b*2+0]);
                        acc[b*2+0] = fmaf(v.z, wreg[i][2][0], acc[b*2+0]);
                        acc[b*2+0] = fmaf(v.w, wreg[i][3][0], acc[b*2+0]);
                        acc[b*2+1] = fmaf(v.x, wreg[i][0][1], acc[b*2+1]);
                        acc[b*2+1] = fmaf(v.y, wreg[i][1][1], acc[b*2+1]);
                        acc[b*2+1] = fmaf(v.z, wreg[i][2][1], acc[b*2+1]);
                        acc[b*2+1] = fmaf(v.w, wreg[i][3][1], acc[b*2+1]);
                    }
                }
            }

#pragma unroll
            for (int o = 0; o < 16; o++) sRed[warp][o][lane] = acc[o];
            __syncwarp();

            const int nxt = cur ^ 1;
            {
                const int o = lane >> 1;
                const int h = lane & 1;
                float s = 0.f;
#pragma unroll
                for (int l = 0; l < 16; l++) s += sRed[warp][o][h * 16 + l];
                s += __shfl_xor_sync(0xffffffffu, s, 1);
                if (h == 0) {
                    int b = o >> 1, j = o & 1;
                    s += (j ? bias1 : bias0);
                    float sn = tanhf(s);
                    g_S[nxt][b * Nn + j0 + j] = sn;
                    if (step == 3) g_H[(b * Tt + t) * Nn + j0 + j] = sn;
                }
            }
            cur ^= 1;
            gridbar();
        }
    }
}

// ---------------- layernorm ----------------
__global__ void __launch_bounds__(256) ln_kernel(
    const float* __restrict__ in, float* __restrict__ outp,
    const float* __restrict__ gamma, const float* __restrict__ beta)
{
    const int row = blockIdx.x;
    const int tid = threadIdx.x;
    float4 v = ((const float4*)(in + row * Nn))[tid];
    float s = v.x + v.y + v.z + v.w;
    float q = v.x*v.x + v.y*v.y + v.z*v.z + v.w*v.w;
#pragma unroll
    for (int off = 16; off; off >>= 1) {
        s += __shfl_xor_sync(0xffffffffu, s, off);
        q += __shfl_xor_sync(0xffffffffu, q, off);
    }
    __shared__ float rs[8], rq[8];
    int lane = tid & 31, w = tid >> 5;
    if (lane == 0) { rs[w] = s; rq[w] = q; }
    __syncthreads();
    float ts = 0.f, tq = 0.f;
#pragma unroll
    for (int i = 0; i < 8; i++) { ts += rs[i]; tq += rq[i]; }
    float m   = ts * (1.f / Nn);
    float var = tq * (1.f / Nn) - m * m;
    float r   = rsqrtf(var + 1e-5f);
    float4 g  = ((const float4*)gamma)[tid];
    float4 be = ((const float4*)beta)[tid];
    float4 o;
    o.x = (v.x - m) * r * g.x + be.x;
    o.y = (v.y - m) * r * g.y + be.y;
    o.z = (v.z - m) * r * g.z + be.z;
    o.w = (v.w - m) * r * g.w + be.w;
    ((float4*)(outp + row * Nn))[tid] = o;
}

// ---------------- tiled fp32 GEMM (phases A and C) ----------------
template <bool GATHER, bool BIAS>
__global__ void __launch_bounds__(256) sgemm128(
    int M, int N, int K,
    const float* __restrict__ A, const float* __restrict__ Bm, float* __restrict__ C,
    const int* __restrict__ ids, const float* __restrict__ bias)
{
    constexpr int BM = 128, BN = 128, BK = 8;
    __shared__ float As[BK][BM];
    __shared__ float Bs[BK][BN];

    const int tid = threadIdx.x;
    const int bm  = blockIdx.y * BM;
    const int bn  = blockIdx.x * BN;

    const int innerRowA = tid >> 1;
    const int innerColA = (tid & 1) * 4;
    const int innerRowB = tid >> 5;
    const int innerColB = (tid & 31) * 4;

    const int tr = tid >> 4;
    const int tc = tid & 15;

    const int arow = bm + innerRowA;
    const int arowBase = (GATHER ? ids[arow] : arow) * K;

    float acc[8][8];
#pragma unroll
    for (int i = 0; i < 8; i++)
#pragma unroll
        for (int j = 0; j < 8; j++) acc[i][j] = 0.f;

    for (int kb = 0; kb < K; kb += BK) {
        float4 a = *(const float4*)(A + arowBase + kb + innerColA);
        float4 b = *(const float4*)(Bm + (kb + innerRowB) * N + bn + innerColB);
        As[innerColA + 0][innerRowA] = a.x;
        As[innerColA + 1][innerRowA] = a.y;
        As[innerColA + 2][innerRowA] = a.z;
        As[innerColA + 3][innerRowA] = a.w;
        *(float4*)&Bs[innerRowB][innerColB] = b;
        __syncthreads();

#pragma unroll
        for (int k = 0; k < BK; k++) {
            float rm[8], rn[8];
#pragma unroll
            for (int i = 0; i < 8; i++) rm[i] = As[k][tr * 8 + i];
#pragma unroll
            for (int j = 0; j < 8; j++) rn[j] = Bs[k][tc * 8 + j];
#pragma unroll
            for (int i = 0; i < 8; i++)
#pragma unroll
                for (int j = 0; j < 8; j++)
                    acc[i][j] = fmaf(rm[i], rn[j], acc[i][j]);
        }
        __syncthreads();
    }

#pragma unroll
    for (int i = 0; i < 8; i++) {
        int crow = (bm + tr * 8 + i) * N + bn + tc * 8;
#pragma unroll
        for (int j4 = 0; j4 < 2; j4++) {
            float4 v;
            v.x = acc[i][j4*4+0]; v.y = acc[i][j4*4+1];
            v.z = acc[i][j4*4+2]; v.w = acc[i][j4*4+3];
            if (BIAS) {
                float4 bb = *(const float4*)(bias + bn + tc * 8 + j4 * 4);
                v.x += bb.x; v.y += bb.y; v.z += bb.z; v.w += bb.w;
            }
            *(float4*)(C + crow + j4 * 4) = v;
        }
    }
}

// ---------------- tf32 producers ----------------
// transpose w_head [E, V] -> [V, E], rounding to tf32
__global__ void __launch_bounds__(256) transpose_tf32_kernel(
    const float* __restrict__ src, float* __restrict__ dst)
{
    __shared__ float tile[32][33];
    const int n0 = blockIdx.x * 32;
    const int k0 = blockIdx.y * 32;
    const int tx = threadIdx.x;
    const int ty = threadIdx.y;
#pragma unroll
    for (int j = 0; j < 32; j += 8)
        tile[ty + j][tx] = src[(size_t)(k0 + ty + j) * Vv + n0 + tx];
    __syncthreads();
#pragma unroll
    for (int j = 0; j < 32; j += 8)
        dst[(size_t)(n0 + ty + j) * Ee + k0 + tx] = tf32r(tile[tx][ty + j]);
}

// in-place tf32 rounding of P
__global__ void __launch_bounds__(256) round_tf32_kernel(float* __restrict__ p, int n)
{
    int i = blockIdx.x * blockDim.x + threadIdx.x;
    if (i < n) p[i] = tf32r(p[i]);
}

// ---------------- TF32 head GEMM (cp.async double-buffered) ----------------
// out[2048,32000] = P @ w_head, single-pass tf32 (operands pre-rounded rna).
constexpr int HSTRf   = 36;                      // smem row stride in floats (conflict-free)
constexpr int HTILEf  = 128 * HSTRf * 4;         // 18432 B per operand tile
constexpr int HSTAGEf = HTILEf * 2;              // 36864 B per stage (A+B)
constexpr int HG_SMEM = HSTAGEf * 2;             // 73728 B

__device__ __forceinline__ uint32_t ldsf(const float* p) {
    return *(const uint32_t*)p;
}
__device__ __forceinline__ void mma_tf32(float* c, const uint32_t* a,
                                         uint32_t b0, uint32_t b1) {
    asm volatile(
        "mma.sync.aligned.m16n8k8.row.col.f32.tf32.tf32.f32 "
        "{%0,%1,%2,%3}, {%4,%5,%6,%7}, {%8,%9}, {%0,%1,%2,%3};"
        : "+f"(c[0]), "+f"(c[1]), "+f"(c[2]), "+f"(c[3])
        : "r"(a[0]), "r"(a[1]), "r"(a[2]), "r"(a[3]), "r"(b0), "r"(b1));
}

__global__ void __launch_bounds__(256) head_mma_kernel(
    const float* __restrict__ A, const float* __restrict__ Bt,
    float* __restrict__ out)
{
    extern __shared__ char hsm[];
    const uint32_t sbase = smem_u32(hsm);

    const int tid  = threadIdx.x;
    const int warp = tid >> 5;
    const int lane = tid & 31;
    const int m0 = blockIdx.y * 128;
    const int n0 = blockIdx.x * 128;
    const int wm = (warp >> 1) * 32;
    const int wn = (warp & 1) * 64;
    const int g  = lane >> 2;
    const int t  = lane & 3;

    // loader mapping: 2 threads per row, 16 floats each
    const int lr = tid >> 1;
    const int lc = (tid & 1) * 16;
    const uint32_t soff = (uint32_t)(lr * HSTRf + lc) * 4;
    const float* gA = A  + (size_t)(m0 + lr) * Ee + lc;
    const float* gB = Bt + (size_t)(n0 + lr) * Ee + lc;

    float c[2][8][4];
#pragma unroll
    for (int i = 0; i < 2; i++)
#pragma unroll
        for (int j = 0; j < 8; j++)
#pragma unroll
            for (int q = 0; q < 4; q++) c[i][j][q] = 0.f;

    // prologue: stage 0 (16 floats/thread/tile = 4 cp16)
    {
        uint32_t dA = sbase + soff;
        uint32_t dB = sbase + HTILEf + soff;
#pragma unroll
        for (int q = 0; q < 4; q++) {
            cp16(dA + q * 16, gA + q * 4);
            cp16(dB + q * 16, gB + q * 4);
        }
        cp_commit();
    }

#pragma unroll 1
    for (int it = 0; it < 24; it++) {
        if (it + 1 < 24) {
            const int st = (it + 1) & 1;
            const int kb = (it + 1) * 32;
            uint32_t dA = sbase + st * HSTAGEf + soff;
            uint32_t dB = sbase + st * HSTAGEf + HTILEf + soff;
#pragma unroll
            for (int q = 0; q < 4; q++) {
                cp16(dA + q * 16, gA + kb + q * 4);
                cp16(dB + q * 16, gB + kb + q * 4);
            }
            cp_commit();
            cp_wait<1>();
        } else {
            cp_wait<0>();
        }
        __syncthreads();

        const float* sA = (const float*)(hsm + (it & 1) * HSTAGEf);
        const float* sB = (const float*)(hsm + (it & 1) * HSTAGEf + HTILEf);

#pragma unroll
        for (int ks = 0; ks < 4; ks++) {
            const int k0 = ks * 8;
            uint32_t a[2][4];
#pragma unroll
            for (int i = 0; i < 2; i++) {
                const float* r0 = &sA[(wm + 16 * i + g) * HSTRf + k0 + t];
                const float* r1 = &sA[(wm + 16 * i + g + 8) * HSTRf + k0 + t];
                a[i][0] = ldsf(r0);
                a[i][1] = ldsf(r1);
                a[i][2] = ldsf(r0 + 4);
                a[i][3] = ldsf(r1 + 4);
            }
#pragma unroll
            for (int j = 0; j < 8; j++) {
                const float* nb = &sB[(wn + 8 * j + g) * HSTRf + k0 + t];
                uint32_t b0 = ldsf(nb);
                uint32_t b1 = ldsf(nb + 4);
                mma_tf32(c[0][j], a[0], b0, b1);
                mma_tf32(c[1][j], a[1], b0, b1);
            }
        }
        __syncthreads();
    }

    // epilogue: direct float2 stores
#pragma unroll
    for (int i = 0; i < 2; i++) {
#pragma unroll
        for (int j = 0; j < 8; j++) {
            int row = m0 + wm + 16 * i + g;
            int col = n0 + wn + 8 * j + 2 * t;
            float2 v0 = make_float2(c[i][j][0], c[i][j][1]);
            float2 v1 = make_float2(c[i][j][2], c[i][j][3]);
            *(float2*)(out + (size_t)row * Vv + col)       = v0;
            *(float2*)(out + (size_t)(row + 8) * Vv + col) = v1;
        }
    }
}

// ---------------- launch ----------------
extern "C" void kernel_launch(void* const* d_in, const int* in_sizes, int n_in,
                              void* d_out, int out_size)
{
    const int*   ids    = (const int*)  d_in[0];
    const float* emb    = (const float*)d_in[1];
    const float* w_in   = (const float*)d_in[2];
    const float* b_in   = (const float*)d_in[3];
    const float* w_bb   = (const float*)d_in[4];
    const float* b_bb   = (const float*)d_in[5];
    const float* gamma  = (const float*)d_in[6];
    const float* beta   = (const float*)d_in[7];
    const float* w_out  = (const float*)d_in[8];
    const float* w_head = (const float*)d_in[9];
    float* out = (float*)d_out;

    float *pX = nullptr, *pH = nullptr, *pHn = nullptr, *pP = nullptr, *pBt = nullptr;
    cudaGetSymbolAddress((void**)&pX,  g_X);
    cudaGetSymbolAddress((void**)&pH,  g_H);
    cudaGetSymbolAddress((void**)&pHn, g_Hn);
    cudaGetSymbolAddress((void**)&pP,  g_P);
    cudaGetSymbolAddress((void**)&pBt, g_Bt);

    cudaFuncSetAttribute(head_mma_kernel,
                         cudaFuncAttributeMaxDynamicSharedMemorySize, HG_SMEM);

    // 0. reset barrier state
    init_barrier_kernel<<<1, 1>>>();

    // 0b. transpose + tf32-round w_head
    {
        dim3 g(Vv / 32, Ee / 32), b(32, 8);
        transpose_tf32_kernel<<<g, b>>>(w_head, pBt);
    }

    // 1. X = emb[ids] @ w_in + b_in
    {
        dim3 g(Nn / 128, BT / 128);
        sgemm128<true, true><<<g, 256>>>(BT, Nn, Ee, emb, w_in, pX, ids, b_in);
    }

    // 2. recurrent scan
    recurrent_kernel<<<RNCTA, RTPB>>>(w_bb, b_bb);

    // 3. layernorm
    ln_kernel<<<BT, 256>>>(pH, pHn, gamma, beta);

    // 4. P = Hn @ w_out
    {
        dim3 g(Ee / 128, BT / 128);
        sgemm128<false, false><<<g, 256>>>(BT, Ee, Nn, pHn, w_out, pP, nullptr, nullptr);
    }

    // 5. tf32-round P in place
    round_tf32_kernel<<<(BT * Ee + 255) / 256, 256>>>(pP, BT * Ee);

    // 6. logits = P @ w_head via single-pass TF32 HMMA
    {
        dim3 g(Vv / 128, BT / 128);
        head_mma_kernel<<<g, 256, HG_SMEM>>>(pP, pBt, out);
    }
}